// round 7
// baseline (speedup 1.0000x reference)
#include <cuda_runtime.h>
#include <cuda_bf16.h>
#include <math.h>
#include <stdint.h>

// Problem constants
#define kE   2048
#define kHQ  32
#define kHKV 8
#define kHD  64
#define kB   2
#define kT   2048
#define kM   (kB * kT)          // 4096 rows (B*T)
#define kKVN (2 * kHKV * kHD)   // 1024

// ---------------------------------------------------------------------------
// Device-global scratch (allocation-free per harness rules)
// ---------------------------------------------------------------------------
__device__ float g_q[kM * kE];       // q projection  (fp32)
__device__ float g_kv[kM * kKVN];    // kv projection (fp32): k [0,512), v [512,1024)
__device__ __nv_bfloat16 g_xhi[kM * kE],     g_xlo[kM * kE];
__device__ __nv_bfloat16 g_wqhi[kE * kE],    g_wqlo[kE * kE];
__device__ __nv_bfloat16 g_wkvhi[kKVN * kE], g_wkvlo[kKVN * kE];
__device__ __nv_bfloat16 g_wohi[kE * kE],    g_wolo[kE * kE];
__device__ __nv_bfloat16 g_aohi[kM * kE],    g_aolo[kM * kE];

// ---------------------------------------------------------------------------
// Helpers
// ---------------------------------------------------------------------------
__device__ __forceinline__ uint32_t smem_u32(const void* p) {
    uint32_t a;
    asm("{ .reg .u64 t; cvta.to.shared.u64 t, %1; cvt.u32.u64 %0, t; }"
        : "=r"(a) : "l"(p));
    return a;
}

__device__ __forceinline__ void cp16(uint32_t saddr, const void* g) {
    asm volatile("cp.async.cg.shared.global [%0], [%1], 16;"
                 :: "r"(saddr), "l"(g) : "memory");
}
#define CP_COMMIT()  asm volatile("cp.async.commit_group;" ::: "memory")
#define CP_WAIT(n)   asm volatile("cp.async.wait_group %0;" :: "n"(n) : "memory")

// Legacy bf16 tensor op: D(16x8,f32) += A(16x16,bf16) * B(16x8,bf16)
__device__ __forceinline__ void mma_bf16(float* d, const uint32_t* a, const uint32_t* b) {
    asm volatile(
        "mma.sync.aligned.m16n8k16.row.col.f32.bf16.bf16.f32 "
        "{%0,%1,%2,%3},{%4,%5,%6,%7},{%8,%9},{%0,%1,%2,%3};\n"
        : "+f"(d[0]), "+f"(d[1]), "+f"(d[2]), "+f"(d[3])
        : "r"(a[0]), "r"(a[1]), "r"(a[2]), "r"(a[3]), "r"(b[0]), "r"(b[1]));
}

// bf16 split: v = hi + lo + O(2^-18 v)
__device__ __forceinline__ void splitbf(float v, __nv_bfloat16& h, __nv_bfloat16& l) {
    h = __float2bfloat16(v);
    l = __float2bfloat16(v - __bfloat162float(h));
}

__global__ __launch_bounds__(256) void split_kernel(
        const float* __restrict__ in, __nv_bfloat16* __restrict__ hi,
        __nv_bfloat16* __restrict__ lo, int n4) {
    int i = blockIdx.x * blockDim.x + threadIdx.x;
    if (i >= n4) return;
    float4 v = ((const float4*)in)[i];
    __nv_bfloat16 h0, h1, h2, h3, l0, l1, l2, l3;
    splitbf(v.x, h0, l0); splitbf(v.y, h1, l1);
    splitbf(v.z, h2, l2); splitbf(v.w, h3, l3);
    __nv_bfloat162* hp = (__nv_bfloat162*)hi;
    __nv_bfloat162* lp = (__nv_bfloat162*)lo;
    hp[2*i]   = __nv_bfloat162(h0, h1);
    hp[2*i+1] = __nv_bfloat162(h2, h3);
    lp[2*i]   = __nv_bfloat162(l0, l1);
    lp[2*i+1] = __nv_bfloat162(l2, l3);
}

// ---------------------------------------------------------------------------
// GEMM: C[M,N] = A[M,K] * W[N,K]^T, bf16x3 on legacy mma.m16n8k16.
// CTA tile 128x128, K-tile 32, 8 warps (warp tile 32x64).
// 3-stage cp.async pipeline (prefetch distance 2).
// Smem planes 128 rows x 16 words, padded to stride 20 (conflict-free).
// ---------------------------------------------------------------------------
#define SPLANE_W 2560                       // 128 * 20 u32 words
#define SPLANE_B (SPLANE_W * 4)             // 10240 bytes
#define STAGE_B  (4 * SPLANE_B)             // Ahi, Alo, Whi, Wlo
#define GEMM_SMEM (3 * STAGE_B)             // 122880 bytes

__global__ __launch_bounds__(256) void gemm_bf3(
        const __nv_bfloat16* __restrict__ Ahi, const __nv_bfloat16* __restrict__ Alo,
        const __nv_bfloat16* __restrict__ Whi, const __nv_bfloat16* __restrict__ Wlo,
        float* __restrict__ C, int N, int K) {
    extern __shared__ char smem[];
    const uint32_t sbase = smem_u32(smem);

    const int tid  = threadIdx.x;
    const int lane = tid & 31;
    const int wid  = tid >> 5;
    const int wm   = wid >> 1;        // 0..3
    const int wn   = wid & 1;         // 0..1
    const int m0   = blockIdx.y * 128;
    const int n0   = blockIdx.x * 128;

    float acc[2][8][4];
#pragma unroll
    for (int i = 0; i < 2; i++)
#pragma unroll
        for (int j = 0; j < 8; j++)
#pragma unroll
            for (int k = 0; k < 4; k++) acc[i][j][k] = 0.f;

    const size_t gs = (size_t)K * 2;  // bytes per global row
    const int crow  = tid >> 1;       // 0..127
    const int cbo   = (tid & 1) << 5; // 0 or 32 bytes within the 64B row

    const char* pA[2] = {(const char*)Ahi, (const char*)Alo};
    const char* pW[2] = {(const char*)Whi, (const char*)Wlo};

    const int NKT = K >> 5;

    auto copy_tile = [&](int s, int kt) {
        const uint32_t st = sbase + s * STAGE_B + crow * 80 + cbo;
        const size_t goA = (size_t)(m0 + crow) * gs + (size_t)kt * 64 + cbo;
        const size_t goW = (size_t)(n0 + crow) * gs + (size_t)kt * 64 + cbo;
#pragma unroll
        for (int pl = 0; pl < 2; pl++) {
            cp16(st + pl * SPLANE_B,             pA[pl] + goA);
            cp16(st + pl * SPLANE_B + 16,        pA[pl] + goA + 16);
            cp16(st + (2 + pl) * SPLANE_B,       pW[pl] + goW);
            cp16(st + (2 + pl) * SPLANE_B + 16,  pW[pl] + goW + 16);
        }
    };

    copy_tile(0, 0); CP_COMMIT();
    if (NKT > 1) { copy_tile(1, 1); CP_COMMIT(); }

    const int rq = lane >> 2;       // 0..7
    const int wc = lane & 3;        // 0..3

    int stage = 0;
    for (int kt = 0; kt < NKT; kt++) {
        if (kt + 2 < NKT) {
            int s2 = stage + 2; if (s2 >= 3) s2 -= 3;
            copy_tile(s2, kt + 2);
            CP_COMMIT();
            CP_WAIT(2);
        } else if (kt + 1 < NKT) {
            CP_WAIT(1);
        } else {
            CP_WAIT(0);
        }
        __syncthreads();

        const uint32_t* base = (const uint32_t*)(smem + stage * STAGE_B);
        const uint32_t* Ah = base;
        const uint32_t* Al = base + SPLANE_W;
        const uint32_t* Wh = base + 2 * SPLANE_W;
        const uint32_t* Wl = base + 3 * SPLANE_W;

#pragma unroll
        for (int ks = 0; ks < 2; ks++) {
            const int s8 = ks * 8 + wc;
            uint32_t ah[2][4], al[2][4];
#pragma unroll
            for (int mt = 0; mt < 2; mt++) {
                const int r = wm * 32 + mt * 16 + rq;
                ah[mt][0] = Ah[r * 20 + s8];
                ah[mt][1] = Ah[(r + 8) * 20 + s8];
                ah[mt][2] = Ah[r * 20 + s8 + 4];
                ah[mt][3] = Ah[(r + 8) * 20 + s8 + 4];
                al[mt][0] = Al[r * 20 + s8];
                al[mt][1] = Al[(r + 8) * 20 + s8];
                al[mt][2] = Al[r * 20 + s8 + 4];
                al[mt][3] = Al[(r + 8) * 20 + s8 + 4];
            }
#pragma unroll
            for (int nt = 0; nt < 8; nt++) {
                const int n = wn * 64 + nt * 8 + rq;
                uint32_t bh[2], bl[2];
                bh[0] = Wh[n * 20 + s8];
                bh[1] = Wh[n * 20 + s8 + 4];
                bl[0] = Wl[n * 20 + s8];
                bl[1] = Wl[n * 20 + s8 + 4];
                mma_bf16(acc[0][nt], ah[0], bl);
                mma_bf16(acc[1][nt], ah[1], bl);
                mma_bf16(acc[0][nt], al[0], bh);
                mma_bf16(acc[1][nt], al[1], bh);
                mma_bf16(acc[0][nt], ah[0], bh);
                mma_bf16(acc[1][nt], ah[1], bh);
            }
        }
        __syncthreads();
        stage++; if (stage == 3) stage = 0;
    }

    // Epilogue (C-fragment layout -> gmem)
#pragma unroll
    for (int mt = 0; mt < 2; mt++) {
        const int r = m0 + wm * 32 + mt * 16 + rq;
#pragma unroll
        for (int nt = 0; nt < 8; nt++) {
            const int c = n0 + wn * 64 + nt * 8 + (wc << 1);
            *(float2*)&C[(size_t)r * N + c]       = make_float2(acc[mt][nt][0], acc[mt][nt][1]);
            *(float2*)&C[(size_t)(r + 8) * N + c] = make_float2(acc[mt][nt][2], acc[mt][nt][3]);
        }
    }
}

// ---------------------------------------------------------------------------
// Flash attention (causal, GQA), tf32 legacy mma (numerics identical to R6).
// v2: 128-row Q tile, 8 warps (256 threads), register prefetch of next K/V.
// ---------------------------------------------------------------------------
__device__ __forceinline__ uint32_t f2tf32(float v) {
    uint32_t r;
    asm("cvt.rna.tf32.f32 %0, %1;" : "=r"(r) : "f"(v));
    return r;
}
__device__ __forceinline__ void mma_tf32(float* d, const uint32_t* a, const uint32_t* b) {
    asm volatile(
        "mma.sync.aligned.m16n8k8.row.col.f32.tf32.tf32.f32 "
        "{%0,%1,%2,%3},{%4,%5,%6,%7},{%8,%9},{%0,%1,%2,%3};\n"
        : "+f"(d[0]), "+f"(d[1]), "+f"(d[2]), "+f"(d[3])
        : "r"(a[0]), "r"(a[1]), "r"(a[2]), "r"(a[3]), "r"(b[0]), "r"(b[1]));
}

#define QS 68   // == 4 (mod 32)
#define VSs 72  // == 8 (mod 32)
#define ATTN_SMEM ((128 * QS * 2 + 64 * QS + 64 * VSs) * 4)   // Qs, Ps, Ks, Vs

__global__ __launch_bounds__(256) void attn_kernel(
        const float* __restrict__ q, const float* __restrict__ kv,
        __nv_bfloat16* __restrict__ aohi, __nv_bfloat16* __restrict__ aolo) {
    extern __shared__ uint32_t sm[];
    uint32_t* Qs = sm;
    uint32_t* Ps = Qs + 128 * QS;
    uint32_t* Ks = Ps + 128 * QS;
    uint32_t* Vs = Ks + 64 * QS;

    const int tid  = threadIdx.x;
    const int lane = tid & 31;
    const int w    = tid >> 5;        // 0..7
    const int qb   = blockIdx.x;      // 128-row query block (0..15)
    const int bh   = blockIdx.y;
    const int b    = bh >> 5;
    const int hq   = bh & 31;
    const int hkv  = hq >> 2;

    const int row0g = qb * 128;       // first global query row of this CTA
    const int ldrow = tid >> 4;       // 0..15
    const int ldcol = (tid & 15) << 2;

    // Load 128-row Q tile, pre-scaled, converted to tf32
#pragma unroll
    for (int p = 0; p < 8; p++) {
        int row = p * 16 + ldrow;
        const float4 v = *(const float4*)&q[((size_t)(b * kT + row0g + row)) * kE + hq * kHD + ldcol];
        *(uint4*)&Qs[row * QS + ldcol] =
            make_uint4(f2tf32(v.x * 0.125f), f2tf32(v.y * 0.125f),
                       f2tf32(v.z * 0.125f), f2tf32(v.w * 0.125f));
    }

    float mrow0 = -INFINITY, mrow1 = -INFINITY;
    float lrow0 = 0.f, lrow1 = 0.f;
    float o[8][4];
#pragma unroll
    for (int nt = 0; nt < 8; nt++)
#pragma unroll
        for (int i = 0; i < 4; i++) o[nt][i] = 0.f;

    const int rloc = w * 16 + (lane >> 2);   // warp's rows rloc, rloc+8 (0..127)
    const int njt  = 2 * qb + 2;             // 64-col K tiles covering causal span

    // Prologue: K/V tile 0 straight to smem
#pragma unroll
    for (int p = 0; p < 4; p++) {
        int row = p * 16 + ldrow;
        size_t base = ((size_t)(b * kT + row)) * kKVN + hkv * kHD + ldcol;
        float4 kvr = *(const float4*)&kv[base];
        float4 vvr = *(const float4*)&kv[base + 512];
        *(uint4*)&Ks[row * QS + ldcol] =
            make_uint4(f2tf32(kvr.x), f2tf32(kvr.y), f2tf32(kvr.z), f2tf32(kvr.w));
        *(uint4*)&Vs[row * VSs + ldcol] =
            make_uint4(f2tf32(vvr.x), f2tf32(vvr.y), f2tf32(vvr.z), f2tf32(vvr.w));
    }
    __syncthreads();

    for (int j = 0; j < njt; j++) {
        // Register prefetch of next K/V tile (LDG hidden under this tile's MMAs)
        float4 rk[4], rv[4];
        if (j + 1 < njt) {
#pragma unroll
            for (int p = 0; p < 4; p++) {
                int row = p * 16 + ldrow;
                size_t base = ((size_t)(b * kT + (j + 1) * 64 + row)) * kKVN + hkv * kHD + ldcol;
                rk[p] = *(const float4*)&kv[base];
                rv[p] = *(const float4*)&kv[base + 512];
            }
        }

        // S = Q * K^T
        float s[8][4];
#pragma unroll
        for (int nt = 0; nt < 8; nt++) { s[nt][0] = s[nt][1] = s[nt][2] = s[nt][3] = 0.f; }

#pragma unroll
        for (int k8 = 0; k8 < 8; k8++) {
            const int kk = k8 * 8 + (lane & 3);
            uint32_t a[4];
            a[0] = Qs[rloc * QS + kk];
            a[1] = Qs[(rloc + 8) * QS + kk];
            a[2] = Qs[rloc * QS + kk + 4];
            a[3] = Qs[(rloc + 8) * QS + kk + 4];
#pragma unroll
            for (int nt = 0; nt < 8; nt++) {
                const int kr = nt * 8 + (lane >> 2);
                uint32_t bb[2];
                bb[0] = Ks[kr * QS + kk];
                bb[1] = Ks[kr * QS + kk + 4];
                mma_tf32(s[nt], a, bb);
            }
        }

        // Causal mask (only the last two tiles can intersect the diagonal)
        if (j >= 2 * qb) {
            const int cbase = j * 64 - row0g;   // col(global) - row0(global)
#pragma unroll
            for (int nt = 0; nt < 8; nt++) {
                int c0 = cbase + nt * 8 + ((lane & 3) << 1);
                if (c0     > rloc)     s[nt][0] = -INFINITY;
                if (c0 + 1 > rloc)     s[nt][1] = -INFINITY;
                if (c0     > rloc + 8) s[nt][2] = -INFINITY;
                if (c0 + 1 > rloc + 8) s[nt][3] = -INFINITY;
            }
        }

        // Online softmax
        float mx0 = -INFINITY, mx1 = -INFINITY;
#pragma unroll
        for (int nt = 0; nt < 8; nt++) {
            mx0 = fmaxf(mx0, fmaxf(s[nt][0], s[nt][1]));
            mx1 = fmaxf(mx1, fmaxf(s[nt][2], s[nt][3]));
        }
        mx0 = fmaxf(mx0, __shfl_xor_sync(0xffffffffu, mx0, 1));
        mx0 = fmaxf(mx0, __shfl_xor_sync(0xffffffffu, mx0, 2));
        mx1 = fmaxf(mx1, __shfl_xor_sync(0xffffffffu, mx1, 1));
        mx1 = fmaxf(mx1, __shfl_xor_sync(0xffffffffu, mx1, 2));

        float mnew0 = fmaxf(mrow0, mx0);
        float mnew1 = fmaxf(mrow1, mx1);
        float alpha0 = __expf(mrow0 - mnew0);
        float alpha1 = __expf(mrow1 - mnew1);
        mrow0 = mnew0; mrow1 = mnew1;

        float sum0 = 0.f, sum1 = 0.f;
#pragma unroll
        for (int nt = 0; nt < 8; nt++) {
            s[nt][0] = __expf(s[nt][0] - mnew0); sum0 += s[nt][0];
            s[nt][1] = __expf(s[nt][1] - mnew0); sum0 += s[nt][1];
            s[nt][2] = __expf(s[nt][2] - mnew1); sum1 += s[nt][2];
            s[nt][3] = __expf(s[nt][3] - mnew1); sum1 += s[nt][3];
        }
        sum0 += __shfl_xor_sync(0xffffffffu, sum0, 1);
        sum0 += __shfl_xor_sync(0xffffffffu, sum0, 2);
        sum1 += __shfl_xor_sync(0xffffffffu, sum1, 1);
        sum1 += __shfl_xor_sync(0xffffffffu, sum1, 2);

        lrow0 = lrow0 * alpha0 + sum0;
        lrow1 = lrow1 * alpha1 + sum1;

#pragma unroll
        for (int nt = 0; nt < 8; nt++) {
            o[nt][0] *= alpha0; o[nt][1] *= alpha0;
            o[nt][2] *= alpha1; o[nt][3] *= alpha1;
        }

        // C-frag -> A-frag via smem (per-warp rows; tf32 at store)
#pragma unroll
        for (int nt = 0; nt < 8; nt++) {
            int pc = nt * 8 + ((lane & 3) << 1);
            Ps[rloc * QS + pc]           = f2tf32(s[nt][0]);
            Ps[rloc * QS + pc + 1]       = f2tf32(s[nt][1]);
            Ps[(rloc + 8) * QS + pc]     = f2tf32(s[nt][2]);
            Ps[(rloc + 8) * QS + pc + 1] = f2tf32(s[nt][3]);
        }
        __syncwarp();

        // O += P * V
#pragma unroll
        for (int k8 = 0; k8 < 8; k8++) {
            const int kk = k8 * 8 + (lane & 3);
            uint32_t a[4];
            a[0] = Ps[rloc * QS + kk];
            a[1] = Ps[(rloc + 8) * QS + kk];
            a[2] = Ps[rloc * QS + kk + 4];
            a[3] = Ps[(rloc + 8) * QS + kk + 4];
#pragma unroll
            for (int nt = 0; nt < 8; nt++) {
                uint32_t bb[2];
                bb[0] = Vs[kk * VSs + nt * 8 + (lane >> 2)];
                bb[1] = Vs[(kk + 4) * VSs + nt * 8 + (lane >> 2)];
                mma_tf32(o[nt], a, bb);
            }
        }
        __syncthreads();   // all warps done reading Ks/Vs

        if (j + 1 < njt) {
#pragma unroll
            for (int p = 0; p < 4; p++) {
                int row = p * 16 + ldrow;
                *(uint4*)&Ks[row * QS + ldcol] =
                    make_uint4(f2tf32(rk[p].x), f2tf32(rk[p].y), f2tf32(rk[p].z), f2tf32(rk[p].w));
                *(uint4*)&Vs[row * VSs + ldcol] =
                    make_uint4(f2tf32(rv[p].x), f2tf32(rv[p].y), f2tf32(rv[p].z), f2tf32(rv[p].w));
            }
        }
        __syncthreads();   // new tile visible
    }

    // Normalize and emit bf16 hi/lo planes for the O-projection
    float inv0 = 1.f / lrow0;
    float inv1 = 1.f / lrow1;
    size_t r0 = (size_t)(b * kT + row0g + rloc) * kE + hq * kHD;
    size_t r1 = (size_t)(b * kT + row0g + rloc + 8) * kE + hq * kHD;
#pragma unroll
    for (int nt = 0; nt < 8; nt++) {
        int c = nt * 8 + ((lane & 3) << 1);
        float f00 = o[nt][0] * inv0, f01 = o[nt][1] * inv0;
        float f10 = o[nt][2] * inv1, f11 = o[nt][3] * inv1;
        __nv_bfloat16 h00, h01, h10, h11, l00, l01, l10, l11;
        splitbf(f00, h00, l00); splitbf(f01, h01, l01);
        splitbf(f10, h10, l10); splitbf(f11, h11, l11);
        *(__nv_bfloat162*)&aohi[r0 + c] = __nv_bfloat162(h00, h01);
        *(__nv_bfloat162*)&aolo[r0 + c] = __nv_bfloat162(l00, l01);
        *(__nv_bfloat162*)&aohi[r1 + c] = __nv_bfloat162(h10, h11);
        *(__nv_bfloat162*)&aolo[r1 + c] = __nv_bfloat162(l10, l11);
    }
}

// ---------------------------------------------------------------------------
// Launch
// ---------------------------------------------------------------------------
extern "C" void kernel_launch(void* const* d_in, const int* in_sizes, int n_in,
                              void* d_out, int out_size) {
    (void)in_sizes; (void)n_in; (void)out_size;
    const float* x   = (const float*)d_in[0];
    const float* Wq  = (const float*)d_in[1];
    const float* Wkv = (const float*)d_in[2];
    const float* Wo  = (const float*)d_in[3];
    float* out = (float*)d_out;

    float *q, *kvb;
    __nv_bfloat16 *xhi, *xlo, *wqhi, *wqlo, *wkvhi, *wkvlo, *wohi, *wolo, *aohi, *aolo;
    cudaGetSymbolAddress((void**)&q,     g_q);
    cudaGetSymbolAddress((void**)&kvb,   g_kv);
    cudaGetSymbolAddress((void**)&xhi,   g_xhi);
    cudaGetSymbolAddress((void**)&xlo,   g_xlo);
    cudaGetSymbolAddress((void**)&wqhi,  g_wqhi);
    cudaGetSymbolAddress((void**)&wqlo,  g_wqlo);
    cudaGetSymbolAddress((void**)&wkvhi, g_wkvhi);
    cudaGetSymbolAddress((void**)&wkvlo, g_wkvlo);
    cudaGetSymbolAddress((void**)&wohi,  g_wohi);
    cudaGetSymbolAddress((void**)&wolo,  g_wolo);
    cudaGetSymbolAddress((void**)&aohi,  g_aohi);
    cudaGetSymbolAddress((void**)&aolo,  g_aolo);

    cudaFuncSetAttribute(gemm_bf3,
                         cudaFuncAttributeMaxDynamicSharedMemorySize, GEMM_SMEM);
    cudaFuncSetAttribute(attn_kernel,
                         cudaFuncAttributeMaxDynamicSharedMemorySize, ATTN_SMEM);

    // Pre-split inputs to bf16 hi/lo planes
    const int nx   = kM * kE / 4,   nwq = kE * kE / 4;
    const int nwkv = kKVN * kE / 4, nwo = kE * kE / 4;
    split_kernel<<<(nx   + 255) / 256, 256>>>(x,   xhi,   xlo,   nx);
    split_kernel<<<(nwq  + 255) / 256, 256>>>(Wq,  wqhi,  wqlo,  nwq);
    split_kernel<<<(nwkv + 255) / 256, 256>>>(Wkv, wkvhi, wkvlo, nwkv);
    split_kernel<<<(nwo  + 255) / 256, 256>>>(Wo,  wohi,  wolo,  nwo);

    // Projections: bf16x3 on legacy tensor cores
    gemm_bf3<<<dim3(kE / 128,   kM / 128), 256, GEMM_SMEM>>>(xhi, xlo, wqhi,  wqlo,  q,   kE,   kE);
    gemm_bf3<<<dim3(kKVN / 128, kM / 128), 256, GEMM_SMEM>>>(xhi, xlo, wkvhi, wkvlo, kvb, kKVN, kE);

    // Attention (tf32 legacy mma, 128-row Q tiles), emits bf16 hi/lo
    attn_kernel<<<dim3(kT / 128, kB * kHQ), 256, ATTN_SMEM>>>(q, kvb, aohi, aolo);

    // O-projection
    gemm_bf3<<<dim3(kE / 128,   kM / 128), 256, GEMM_SMEM>>>(aohi, aolo, wohi, wolo, out, kE, kE);
}

// round 8
// speedup vs baseline: 1.1119x; 1.1119x over previous
#include <cuda_runtime.h>
#include <cuda_bf16.h>
#include <math.h>
#include <stdint.h>

// Problem constants
#define kE   2048
#define kHQ  32
#define kHKV 8
#define kHD  64
#define kB   2
#define kT   2048
#define kM   (kB * kT)          // 4096 rows (B*T)
#define kKVN (2 * kHKV * kHD)   // 1024

// ---------------------------------------------------------------------------
// Device-global scratch (allocation-free per harness rules)
// ---------------------------------------------------------------------------
__device__ float g_q[kM * kE];       // q projection  (fp32)
__device__ float g_kv[kM * kKVN];    // kv projection (fp32): k [0,512), v [512,1024)
__device__ __nv_bfloat16 g_xhi[kM * kE],     g_xlo[kM * kE];
__device__ __nv_bfloat16 g_wqhi[kE * kE],    g_wqlo[kE * kE];
__device__ __nv_bfloat16 g_wkvhi[kKVN * kE], g_wkvlo[kKVN * kE];
__device__ __nv_bfloat16 g_wohi[kE * kE],    g_wolo[kE * kE];
__device__ __nv_bfloat16 g_aohi[kM * kE],    g_aolo[kM * kE];

// ---------------------------------------------------------------------------
// Helpers
// ---------------------------------------------------------------------------
__device__ __forceinline__ uint32_t smem_u32(const void* p) {
    uint32_t a;
    asm("{ .reg .u64 t; cvta.to.shared.u64 t, %1; cvt.u32.u64 %0, t; }"
        : "=r"(a) : "l"(p));
    return a;
}

__device__ __forceinline__ void cp16(uint32_t saddr, const void* g) {
    asm volatile("cp.async.cg.shared.global [%0], [%1], 16;"
                 :: "r"(saddr), "l"(g) : "memory");
}
#define CP_COMMIT()  asm volatile("cp.async.commit_group;" ::: "memory")
#define CP_WAIT(n)   asm volatile("cp.async.wait_group %0;" :: "n"(n) : "memory")

// Legacy bf16 tensor op: D(16x8,f32) += A(16x16,bf16) * B(16x8,bf16)
__device__ __forceinline__ void mma_bf16(float* d, const uint32_t* a, const uint32_t* b) {
    asm volatile(
        "mma.sync.aligned.m16n8k16.row.col.f32.bf16.bf16.f32 "
        "{%0,%1,%2,%3},{%4,%5,%6,%7},{%8,%9},{%0,%1,%2,%3};\n"
        : "+f"(d[0]), "+f"(d[1]), "+f"(d[2]), "+f"(d[3])
        : "r"(a[0]), "r"(a[1]), "r"(a[2]), "r"(a[3]), "r"(b[0]), "r"(b[1]));
}

// bf16 split: v = hi + lo + O(2^-18 v)
__device__ __forceinline__ void splitbf(float v, __nv_bfloat16& h, __nv_bfloat16& l) {
    h = __float2bfloat16(v);
    l = __float2bfloat16(v - __bfloat162float(h));
}

__global__ __launch_bounds__(256) void split_kernel(
        const float* __restrict__ in, __nv_bfloat16* __restrict__ hi,
        __nv_bfloat16* __restrict__ lo, int n4) {
    int i = blockIdx.x * blockDim.x + threadIdx.x;
    if (i >= n4) return;
    float4 v = ((const float4*)in)[i];
    __nv_bfloat16 h0, h1, h2, h3, l0, l1, l2, l3;
    splitbf(v.x, h0, l0); splitbf(v.y, h1, l1);
    splitbf(v.z, h2, l2); splitbf(v.w, h3, l3);
    __nv_bfloat162* hp = (__nv_bfloat162*)hi;
    __nv_bfloat162* lp = (__nv_bfloat162*)lo;
    hp[2*i]   = __nv_bfloat162(h0, h1);
    hp[2*i+1] = __nv_bfloat162(h2, h3);
    lp[2*i]   = __nv_bfloat162(l0, l1);
    lp[2*i+1] = __nv_bfloat162(l2, l3);
}

// ---------------------------------------------------------------------------
// GEMM: C[M,N] = A[M,K] * W[N,K]^T, bf16x3 on legacy mma.m16n8k16.
// (Exact R6 winner: 2-stage cp.async pipeline, CTA 128x128, K-tile 32.)
// ---------------------------------------------------------------------------
#define SPLANE_W 2560                       // 128 * 20 u32 words
#define SPLANE_B (SPLANE_W * 4)             // 10240 bytes
#define STAGE_B  (4 * SPLANE_B)             // Ahi, Alo, Whi, Wlo
#define GEMM_SMEM (2 * STAGE_B)             // 81920 bytes

__global__ __launch_bounds__(256) void gemm_bf3(
        const __nv_bfloat16* __restrict__ Ahi, const __nv_bfloat16* __restrict__ Alo,
        const __nv_bfloat16* __restrict__ Whi, const __nv_bfloat16* __restrict__ Wlo,
        float* __restrict__ C, int N, int K) {
    extern __shared__ char smem[];
    const uint32_t sbase = smem_u32(smem);

    const int tid  = threadIdx.x;
    const int lane = tid & 31;
    const int wid  = tid >> 5;
    const int wm   = wid >> 1;        // 0..3
    const int wn   = wid & 1;         // 0..1
    const int m0   = blockIdx.y * 128;
    const int n0   = blockIdx.x * 128;

    float acc[2][8][4];
#pragma unroll
    for (int i = 0; i < 2; i++)
#pragma unroll
        for (int j = 0; j < 8; j++)
#pragma unroll
            for (int k = 0; k < 4; k++) acc[i][j][k] = 0.f;

    const size_t gs = (size_t)K * 2;  // bytes per global row
    const int crow  = tid >> 1;       // 0..127
    const int cbo   = (tid & 1) << 5; // 0 or 32 bytes

    const char* pA[2] = {(const char*)Ahi, (const char*)Alo};
    const char* pW[2] = {(const char*)Whi, (const char*)Wlo};

    const int NKT = K >> 5;

    auto copy_tile = [&](int s, int kt) {
        const uint32_t st = sbase + s * STAGE_B + crow * 80 + cbo;
        const size_t goA = (size_t)(m0 + crow) * gs + (size_t)kt * 64 + cbo;
        const size_t goW = (size_t)(n0 + crow) * gs + (size_t)kt * 64 + cbo;
#pragma unroll
        for (int pl = 0; pl < 2; pl++) {
            cp16(st + pl * SPLANE_B,             pA[pl] + goA);
            cp16(st + pl * SPLANE_B + 16,        pA[pl] + goA + 16);
            cp16(st + (2 + pl) * SPLANE_B,       pW[pl] + goW);
            cp16(st + (2 + pl) * SPLANE_B + 16,  pW[pl] + goW + 16);
        }
    };

    copy_tile(0, 0);
    CP_COMMIT();

    const int rq = lane >> 2;       // 0..7
    const int wc = lane & 3;        // 0..3

    for (int kt = 0; kt < NKT; kt++) {
        if (kt + 1 < NKT) {
            copy_tile((kt + 1) & 1, kt + 1);
            CP_COMMIT();
            CP_WAIT(1);
        } else {
            CP_WAIT(0);
        }
        __syncthreads();

        const uint32_t* base = (const uint32_t*)(smem + (kt & 1) * STAGE_B);
        const uint32_t* Ah = base;
        const uint32_t* Al = base + SPLANE_W;
        const uint32_t* Wh = base + 2 * SPLANE_W;
        const uint32_t* Wl = base + 3 * SPLANE_W;

#pragma unroll
        for (int ks = 0; ks < 2; ks++) {
            const int s8 = ks * 8 + wc;
            uint32_t ah[2][4], al[2][4];
#pragma unroll
            for (int mt = 0; mt < 2; mt++) {
                const int r = wm * 32 + mt * 16 + rq;
                ah[mt][0] = Ah[r * 20 + s8];
                ah[mt][1] = Ah[(r + 8) * 20 + s8];
                ah[mt][2] = Ah[r * 20 + s8 + 4];
                ah[mt][3] = Ah[(r + 8) * 20 + s8 + 4];
                al[mt][0] = Al[r * 20 + s8];
                al[mt][1] = Al[(r + 8) * 20 + s8];
                al[mt][2] = Al[r * 20 + s8 + 4];
                al[mt][3] = Al[(r + 8) * 20 + s8 + 4];
            }
#pragma unroll
            for (int nt = 0; nt < 8; nt++) {
                const int n = wn * 64 + nt * 8 + rq;
                uint32_t bh[2], bl[2];
                bh[0] = Wh[n * 20 + s8];
                bh[1] = Wh[n * 20 + s8 + 4];
                bl[0] = Wl[n * 20 + s8];
                bl[1] = Wl[n * 20 + s8 + 4];
                mma_bf16(acc[0][nt], ah[0], bl);
                mma_bf16(acc[1][nt], ah[1], bl);
                mma_bf16(acc[0][nt], al[0], bh);
                mma_bf16(acc[1][nt], al[1], bh);
                mma_bf16(acc[0][nt], ah[0], bh);
                mma_bf16(acc[1][nt], ah[1], bh);
            }
        }
        __syncthreads();
    }

#pragma unroll
    for (int mt = 0; mt < 2; mt++) {
        const int r = m0 + wm * 32 + mt * 16 + rq;
#pragma unroll
        for (int nt = 0; nt < 8; nt++) {
            const int c = n0 + wn * 64 + nt * 8 + (wc << 1);
            *(float2*)&C[(size_t)r * N + c]       = make_float2(acc[mt][nt][0], acc[mt][nt][1]);
            *(float2*)&C[(size_t)(r + 8) * N + c] = make_float2(acc[mt][nt][2], acc[mt][nt][3]);
        }
    }
}

// ---------------------------------------------------------------------------
// Flash attention (causal, GQA), tf32 legacy mma — numerics identical to R6.
// v3: one CTA serves TWO query heads sharing the same kv head.
//   warps 0-3 -> head 2i, warps 4-7 -> head 2i+1; K/V filled once, used twice.
//   Per-warp compute loop is bit-identical to the R6 64-row kernel.
// ---------------------------------------------------------------------------
__device__ __forceinline__ uint32_t f2tf32(float v) {
    uint32_t r;
    asm("cvt.rna.tf32.f32 %0, %1;" : "=r"(r) : "f"(v));
    return r;
}
__device__ __forceinline__ void mma_tf32(float* d, const uint32_t* a, const uint32_t* b) {
    asm volatile(
        "mma.sync.aligned.m16n8k8.row.col.f32.tf32.tf32.f32 "
        "{%0,%1,%2,%3},{%4,%5,%6,%7},{%8,%9},{%0,%1,%2,%3};\n"
        : "+f"(d[0]), "+f"(d[1]), "+f"(d[2]), "+f"(d[3])
        : "r"(a[0]), "r"(a[1]), "r"(a[2]), "r"(a[3]), "r"(b[0]), "r"(b[1]));
}

#define QS 68   // == 4 (mod 32)
#define VSs 72  // == 8 (mod 32)
// Qs[2 heads], Ps[2 heads], Ks, Vs
#define ATTN_SMEM ((2 * 64 * QS + 2 * 64 * QS + 64 * QS + 64 * VSs) * 4)

__global__ __launch_bounds__(256) void attn_kernel(
        const float* __restrict__ q, const float* __restrict__ kv,
        __nv_bfloat16* __restrict__ aohi, __nv_bfloat16* __restrict__ aolo) {
    extern __shared__ uint32_t sm[];
    uint32_t* QsAll = sm;                       // 2 * 64 * QS
    uint32_t* PsAll = QsAll + 2 * 64 * QS;      // 2 * 64 * QS
    uint32_t* Ks    = PsAll + 2 * 64 * QS;      // 64 * QS
    uint32_t* Vs    = Ks + 64 * QS;             // 64 * VSs

    const int tid  = threadIdx.x;
    const int lane = tid & 31;
    const int w    = tid >> 5;          // 0..7
    const int wg   = w >> 2;            // head sub-index 0/1
    const int wl   = w & 3;             // warp within head
    const int qb   = blockIdx.x;        // 64-row query block
    const int pidx = blockIdx.y;        // (b, head-pair): 0..31
    const int b    = pidx >> 4;
    const int hp   = pidx & 15;         // head pair 0..15
    const int hq   = hp * 2 + wg;       // this warp's query head
    const int hkv  = hp >> 1;           // shared kv head (== hq>>2 for both)

    uint32_t* Qs = QsAll + wg * (64 * QS);
    uint32_t* Ps = PsAll + wg * (64 * QS);

    // ---- Load both heads' Q tiles (threads 0-127 -> head 0, 128-255 -> head 1)
    {
        const int half  = tid >> 7;               // == wg
        const int hrow  = (tid & 127) >> 4;       // 0..7
        const int hcol  = (tid & 15) << 2;        // 0..60
        const int hqh   = hp * 2 + half;
        uint32_t* Qdst  = QsAll + half * (64 * QS);
#pragma unroll
        for (int p = 0; p < 8; p++) {
            int row = p * 8 + hrow;
            const float4 v = *(const float4*)
                &q[((size_t)(b * kT + qb * 64 + row)) * kE + hqh * kHD + hcol];
            *(uint4*)&Qdst[row * QS + hcol] =
                make_uint4(f2tf32(v.x * 0.125f), f2tf32(v.y * 0.125f),
                           f2tf32(v.z * 0.125f), f2tf32(v.w * 0.125f));
        }
    }

    float mrow0 = -INFINITY, mrow1 = -INFINITY;
    float lrow0 = 0.f, lrow1 = 0.f;
    float o[8][4];
#pragma unroll
    for (int nt = 0; nt < 8; nt++)
#pragma unroll
        for (int i = 0; i < 4; i++) o[nt][i] = 0.f;

    const int rloc  = wl * 16 + (lane >> 2);   // warp's rows rloc, rloc+8 (0..63)
    const int ldrow = tid >> 4;                // 0..15 (all 256 threads fill K/V)
    const int ldcol = (tid & 15) << 2;         // 0..60

    for (int j = 0; j <= qb; j++) {
        // Fill shared K/V tile (64x64 each) once for both heads
#pragma unroll
        for (int p = 0; p < 4; p++) {
            int row = p * 16 + ldrow;
            size_t base = ((size_t)(b * kT + j * 64 + row)) * kKVN + hkv * kHD + ldcol;
            float4 kvr = *(const float4*)&kv[base];
            float4 vvr = *(const float4*)&kv[base + 512];
            *(uint4*)&Ks[row * QS + ldcol] =
                make_uint4(f2tf32(kvr.x), f2tf32(kvr.y), f2tf32(kvr.z), f2tf32(kvr.w));
            *(uint4*)&Vs[row * VSs + ldcol] =
                make_uint4(f2tf32(vvr.x), f2tf32(vvr.y), f2tf32(vvr.z), f2tf32(vvr.w));
        }
        __syncthreads();

        // S = Q * K^T (this warp: 16 rows x 64 cols of its head)
        float s[8][4];
#pragma unroll
        for (int nt = 0; nt < 8; nt++) { s[nt][0] = s[nt][1] = s[nt][2] = s[nt][3] = 0.f; }

#pragma unroll
        for (int k8 = 0; k8 < 8; k8++) {
            const int kk = k8 * 8 + (lane & 3);
            uint32_t a[4];
            a[0] = Qs[rloc * QS + kk];
            a[1] = Qs[(rloc + 8) * QS + kk];
            a[2] = Qs[rloc * QS + kk + 4];
            a[3] = Qs[(rloc + 8) * QS + kk + 4];
#pragma unroll
            for (int nt = 0; nt < 8; nt++) {
                const int kr = nt * 8 + (lane >> 2);
                uint32_t bb[2];
                bb[0] = Ks[kr * QS + kk];
                bb[1] = Ks[kr * QS + kk + 4];
                mma_tf32(s[nt], a, bb);
            }
        }

        // Causal mask on the diagonal block
        if (j == qb) {
#pragma unroll
            for (int nt = 0; nt < 8; nt++) {
                int c0 = nt * 8 + ((lane & 3) << 1);
                if (c0     > rloc)     s[nt][0] = -INFINITY;
                if (c0 + 1 > rloc)     s[nt][1] = -INFINITY;
                if (c0     > rloc + 8) s[nt][2] = -INFINITY;
                if (c0 + 1 > rloc + 8) s[nt][3] = -INFINITY;
            }
        }

        // Online softmax
        float mx0 = -INFINITY, mx1 = -INFINITY;
#pragma unroll
        for (int nt = 0; nt < 8; nt++) {
            mx0 = fmaxf(mx0, fmaxf(s[nt][0], s[nt][1]));
            mx1 = fmaxf(mx1, fmaxf(s[nt][2], s[nt][3]));
        }
        mx0 = fmaxf(mx0, __shfl_xor_sync(0xffffffffu, mx0, 1));
        mx0 = fmaxf(mx0, __shfl_xor_sync(0xffffffffu, mx0, 2));
        mx1 = fmaxf(mx1, __shfl_xor_sync(0xffffffffu, mx1, 1));
        mx1 = fmaxf(mx1, __shfl_xor_sync(0xffffffffu, mx1, 2));

        float mnew0 = fmaxf(mrow0, mx0);
        float mnew1 = fmaxf(mrow1, mx1);
        float alpha0 = __expf(mrow0 - mnew0);
        float alpha1 = __expf(mrow1 - mnew1);
        mrow0 = mnew0; mrow1 = mnew1;

        float sum0 = 0.f, sum1 = 0.f;
#pragma unroll
        for (int nt = 0; nt < 8; nt++) {
            s[nt][0] = __expf(s[nt][0] - mnew0); sum0 += s[nt][0];
            s[nt][1] = __expf(s[nt][1] - mnew0); sum0 += s[nt][1];
            s[nt][2] = __expf(s[nt][2] - mnew1); sum1 += s[nt][2];
            s[nt][3] = __expf(s[nt][3] - mnew1); sum1 += s[nt][3];
        }
        sum0 += __shfl_xor_sync(0xffffffffu, sum0, 1);
        sum0 += __shfl_xor_sync(0xffffffffu, sum0, 2);
        sum1 += __shfl_xor_sync(0xffffffffu, sum1, 1);
        sum1 += __shfl_xor_sync(0xffffffffu, sum1, 2);

        lrow0 = lrow0 * alpha0 + sum0;
        lrow1 = lrow1 * alpha1 + sum1;

#pragma unroll
        for (int nt = 0; nt < 8; nt++) {
            o[nt][0] *= alpha0; o[nt][1] *= alpha0;
            o[nt][2] *= alpha1; o[nt][3] *= alpha1;
        }

        // C-frag -> A-frag via this head's Ps region (per-warp rows)
#pragma unroll
        for (int nt = 0; nt < 8; nt++) {
            int pc = nt * 8 + ((lane & 3) << 1);
            Ps[rloc * QS + pc]           = f2tf32(s[nt][0]);
            Ps[rloc * QS + pc + 1]       = f2tf32(s[nt][1]);
            Ps[(rloc + 8) * QS + pc]     = f2tf32(s[nt][2]);
            Ps[(rloc + 8) * QS + pc + 1] = f2tf32(s[nt][3]);
        }
        __syncwarp();

        // O += P * V
#pragma unroll
        for (int k8 = 0; k8 < 8; k8++) {
            const int kk = k8 * 8 + (lane & 3);
            uint32_t a[4];
            a[0] = Ps[rloc * QS + kk];
            a[1] = Ps[(rloc + 8) * QS + kk];
            a[2] = Ps[rloc * QS + kk + 4];
            a[3] = Ps[(rloc + 8) * QS + kk + 4];
#pragma unroll
            for (int nt = 0; nt < 8; nt++) {
                uint32_t bb[2];
                bb[0] = Vs[kk * VSs + nt * 8 + (lane >> 2)];
                bb[1] = Vs[(kk + 4) * VSs + nt * 8 + (lane >> 2)];
                mma_tf32(o[nt], a, bb);
            }
        }
        __syncthreads();   // all warps done reading Ks/Vs before next fill
    }

    // Normalize and emit bf16 hi/lo planes for the O-projection
    float inv0 = 1.f / lrow0;
    float inv1 = 1.f / lrow1;
    size_t r0 = (size_t)(b * kT + qb * 64 + rloc) * kE + hq * kHD;
    size_t r1 = (size_t)(b * kT + qb * 64 + rloc + 8) * kE + hq * kHD;
#pragma unroll
    for (int nt = 0; nt < 8; nt++) {
        int c = nt * 8 + ((lane & 3) << 1);
        float f00 = o[nt][0] * inv0, f01 = o[nt][1] * inv0;
        float f10 = o[nt][2] * inv1, f11 = o[nt][3] * inv1;
        __nv_bfloat16 h00, h01, h10, h11, l00, l01, l10, l11;
        splitbf(f00, h00, l00); splitbf(f01, h01, l01);
        splitbf(f10, h10, l10); splitbf(f11, h11, l11);
        *(__nv_bfloat162*)&aohi[r0 + c] = __nv_bfloat162(h00, h01);
        *(__nv_bfloat162*)&aolo[r0 + c] = __nv_bfloat162(l00, l01);
        *(__nv_bfloat162*)&aohi[r1 + c] = __nv_bfloat162(h10, h11);
        *(__nv_bfloat162*)&aolo[r1 + c] = __nv_bfloat162(l10, l11);
    }
}

// ---------------------------------------------------------------------------
// Launch
// ---------------------------------------------------------------------------
extern "C" void kernel_launch(void* const* d_in, const int* in_sizes, int n_in,
                              void* d_out, int out_size) {
    (void)in_sizes; (void)n_in; (void)out_size;
    const float* x   = (const float*)d_in[0];
    const float* Wq  = (const float*)d_in[1];
    const float* Wkv = (const float*)d_in[2];
    const float* Wo  = (const float*)d_in[3];
    float* out = (float*)d_out;

    float *q, *kvb;
    __nv_bfloat16 *xhi, *xlo, *wqhi, *wqlo, *wkvhi, *wkvlo, *wohi, *wolo, *aohi, *aolo;
    cudaGetSymbolAddress((void**)&q,     g_q);
    cudaGetSymbolAddress((void**)&kvb,   g_kv);
    cudaGetSymbolAddress((void**)&xhi,   g_xhi);
    cudaGetSymbolAddress((void**)&xlo,   g_xlo);
    cudaGetSymbolAddress((void**)&wqhi,  g_wqhi);
    cudaGetSymbolAddress((void**)&wqlo,  g_wqlo);
    cudaGetSymbolAddress((void**)&wkvhi, g_wkvhi);
    cudaGetSymbolAddress((void**)&wkvlo, g_wkvlo);
    cudaGetSymbolAddress((void**)&wohi,  g_wohi);
    cudaGetSymbolAddress((void**)&wolo,  g_wolo);
    cudaGetSymbolAddress((void**)&aohi,  g_aohi);
    cudaGetSymbolAddress((void**)&aolo,  g_aolo);

    cudaFuncSetAttribute(gemm_bf3,
                         cudaFuncAttributeMaxDynamicSharedMemorySize, GEMM_SMEM);
    cudaFuncSetAttribute(attn_kernel,
                         cudaFuncAttributeMaxDynamicSharedMemorySize, ATTN_SMEM);

    // Pre-split inputs to bf16 hi/lo planes
    const int nx   = kM * kE / 4,   nwq = kE * kE / 4;
    const int nwkv = kKVN * kE / 4, nwo = kE * kE / 4;
    split_kernel<<<(nx   + 255) / 256, 256>>>(x,   xhi,   xlo,   nx);
    split_kernel<<<(nwq  + 255) / 256, 256>>>(Wq,  wqhi,  wqlo,  nwq);
    split_kernel<<<(nwkv + 255) / 256, 256>>>(Wkv, wkvhi, wkvlo, nwkv);
    split_kernel<<<(nwo  + 255) / 256, 256>>>(Wo,  wohi,  wolo,  nwo);

    // Projections: bf16x3 on legacy tensor cores (R6 config)
    gemm_bf3<<<dim3(kE / 128,   kM / 128), 256, GEMM_SMEM>>>(xhi, xlo, wqhi,  wqlo,  q,   kE,   kE);
    gemm_bf3<<<dim3(kKVN / 128, kM / 128), 256, GEMM_SMEM>>>(xhi, xlo, wkvhi, wkvlo, kvb, kKVN, kE);

    // Attention: 2 query heads per CTA share one K/V stream
    attn_kernel<<<dim3(kT / 64, kB * kHQ / 2), 256, ATTN_SMEM>>>(q, kvb, aohi, aolo);

    // O-projection
    gemm_bf3<<<dim3(kE / 128,   kM / 128), 256, GEMM_SMEM>>>(aohi, aolo, wohi, wolo, out, kE, kE);
}

// round 9
// speedup vs baseline: 1.1222x; 1.0092x over previous
#include <cuda_runtime.h>
#include <cuda_bf16.h>
#include <math.h>
#include <stdint.h>

// Problem constants
#define kE   2048
#define kHQ  32
#define kHKV 8
#define kHD  64
#define kB   2
#define kT   2048
#define kM   (kB * kT)          // 4096 rows (B*T)
#define kKVN (2 * kHKV * kHD)   // 1024

// ---------------------------------------------------------------------------
// Device-global scratch (allocation-free per harness rules)
// ---------------------------------------------------------------------------
__device__ float g_q[kM * kE];       // q projection  (fp32)
__device__ float g_kv[kM * kKVN];    // kv projection (fp32): k [0,512), v [512,1024)
__device__ __nv_bfloat16 g_xhi[kM * kE],     g_xlo[kM * kE];
__device__ __nv_bfloat16 g_wqhi[kE * kE],    g_wqlo[kE * kE];
__device__ __nv_bfloat16 g_wkvhi[kKVN * kE], g_wkvlo[kKVN * kE];
__device__ __nv_bfloat16 g_wohi[kE * kE],    g_wolo[kE * kE];
__device__ __nv_bfloat16 g_aohi[kM * kE],    g_aolo[kM * kE];

// ---------------------------------------------------------------------------
// Helpers
// ---------------------------------------------------------------------------
__device__ __forceinline__ uint32_t smem_u32(const void* p) {
    uint32_t a;
    asm("{ .reg .u64 t; cvta.to.shared.u64 t, %1; cvt.u32.u64 %0, t; }"
        : "=r"(a) : "l"(p));
    return a;
}

__device__ __forceinline__ void cp16(uint32_t saddr, const void* g) {
    asm volatile("cp.async.cg.shared.global [%0], [%1], 16;"
                 :: "r"(saddr), "l"(g) : "memory");
}
#define CP_COMMIT()  asm volatile("cp.async.commit_group;" ::: "memory")
#define CP_WAIT(n)   asm volatile("cp.async.wait_group %0;" :: "n"(n) : "memory")

// ldmatrix x4: one instruction loads 4 fragment registers
#define LDSM4(r, addr)                                                        \
    asm volatile("ldmatrix.sync.aligned.m8n8.x4.shared.b16 {%0,%1,%2,%3}, [%4];" \
        : "=r"((r)[0]), "=r"((r)[1]), "=r"((r)[2]), "=r"((r)[3]) : "r"(addr))

// Legacy bf16 tensor op: D(16x8,f32) += A(16x16,bf16) * B(16x8,bf16)
__device__ __forceinline__ void mma_bf16(float* d, const uint32_t* a, const uint32_t* b) {
    asm volatile(
        "mma.sync.aligned.m16n8k16.row.col.f32.bf16.bf16.f32 "
        "{%0,%1,%2,%3},{%4,%5,%6,%7},{%8,%9},{%0,%1,%2,%3};\n"
        : "+f"(d[0]), "+f"(d[1]), "+f"(d[2]), "+f"(d[3])
        : "r"(a[0]), "r"(a[1]), "r"(a[2]), "r"(a[3]), "r"(b[0]), "r"(b[1]));
}

// bf16 split: v = hi + lo + O(2^-18 v)
__device__ __forceinline__ void splitbf(float v, __nv_bfloat16& h, __nv_bfloat16& l) {
    h = __float2bfloat16(v);
    l = __float2bfloat16(v - __bfloat162float(h));
}

__global__ __launch_bounds__(256) void split_kernel(
        const float* __restrict__ in, __nv_bfloat16* __restrict__ hi,
        __nv_bfloat16* __restrict__ lo, int n4) {
    int i = blockIdx.x * blockDim.x + threadIdx.x;
    if (i >= n4) return;
    float4 v = ((const float4*)in)[i];
    __nv_bfloat16 h0, h1, h2, h3, l0, l1, l2, l3;
    splitbf(v.x, h0, l0); splitbf(v.y, h1, l1);
    splitbf(v.z, h2, l2); splitbf(v.w, h3, l3);
    __nv_bfloat162* hp = (__nv_bfloat162*)hi;
    __nv_bfloat162* lp = (__nv_bfloat162*)lo;
    hp[2*i]   = __nv_bfloat162(h0, h1);
    hp[2*i+1] = __nv_bfloat162(h2, h3);
    lp[2*i]   = __nv_bfloat162(l0, l1);
    lp[2*i+1] = __nv_bfloat162(l2, l3);
}

// ---------------------------------------------------------------------------
// GEMM: C[M,N] = A[M,K] * W[N,K]^T, bf16x3, mma.m16n8k16 + ldmatrix fragments.
// CTA 128x128, K-tile 32, 8 warps, 2-stage cp.async pipeline.
// Plane: 128 rows x 20-word stride (80B). LDSM rows hit banks
// {0,20,8,28,16,4,24,12} -> conflict-free.
// ---------------------------------------------------------------------------
#define SPLANE_W 2560                       // 128 * 20 u32 words
#define SPLANE_B (SPLANE_W * 4)             // 10240 bytes
#define STAGE_B  (4 * SPLANE_B)             // Ahi, Alo, Whi, Wlo
#define GEMM_SMEM (2 * STAGE_B)             // 81920 bytes

__global__ __launch_bounds__(256) void gemm_bf3(
        const __nv_bfloat16* __restrict__ Ahi, const __nv_bfloat16* __restrict__ Alo,
        const __nv_bfloat16* __restrict__ Whi, const __nv_bfloat16* __restrict__ Wlo,
        float* __restrict__ C, int N, int K) {
    extern __shared__ char smem[];
    const uint32_t sbase = smem_u32(smem);

    const int tid  = threadIdx.x;
    const int lane = tid & 31;
    const int wid  = tid >> 5;
    const int wm   = wid >> 1;        // 0..3
    const int wn   = wid & 1;         // 0..1
    const int m0   = blockIdx.y * 128;
    const int n0   = blockIdx.x * 128;

    float acc[2][8][4];
#pragma unroll
    for (int i = 0; i < 2; i++)
#pragma unroll
        for (int j = 0; j < 8; j++)
#pragma unroll
            for (int k = 0; k < 4; k++) acc[i][j][k] = 0.f;

    const size_t gs = (size_t)K * 2;  // bytes per global row
    const int crow  = tid >> 1;       // 0..127
    const int cbo   = (tid & 1) << 5; // 0 or 32 bytes

    const char* pA[2] = {(const char*)Ahi, (const char*)Alo};
    const char* pW[2] = {(const char*)Whi, (const char*)Wlo};

    const int NKT = K >> 5;

    auto copy_tile = [&](int s, int kt) {
        const uint32_t st = sbase + s * STAGE_B + crow * 80 + cbo;
        const size_t goA = (size_t)(m0 + crow) * gs + (size_t)kt * 64 + cbo;
        const size_t goW = (size_t)(n0 + crow) * gs + (size_t)kt * 64 + cbo;
#pragma unroll
        for (int pl = 0; pl < 2; pl++) {
            cp16(st + pl * SPLANE_B,             pA[pl] + goA);
            cp16(st + pl * SPLANE_B + 16,        pA[pl] + goA + 16);
            cp16(st + (2 + pl) * SPLANE_B,       pW[pl] + goW);
            cp16(st + (2 + pl) * SPLANE_B + 16,  pW[pl] + goW + 16);
        }
    };

    copy_tile(0, 0);
    CP_COMMIT();

    // ldmatrix lane-address components
    const int lr8 = lane & 7;
    const int r8  = (lane >> 3) & 1;    // +8 rows  (matrices 1,3)
    const int c4  = (lane >> 4) & 1;    // +4 words (matrices 2,3)
    // byte offsets within a plane (add ks*32 for the second k16-step)
    const uint32_t aoff0 = (uint32_t)((wm * 32 + lr8 + 8 * r8) * 80 + c4 * 16);
    const uint32_t aoff1 = aoff0 + 16 * 80;
    uint32_t boff[4];
#pragma unroll
    for (int np = 0; np < 4; np++)
        boff[np] = (uint32_t)((wn * 64 + np * 16 + lr8 + 8 * r8) * 80 + c4 * 16);

    const int rq = lane >> 2;
    const int wc = lane & 3;

    for (int kt = 0; kt < NKT; kt++) {
        if (kt + 1 < NKT) {
            copy_tile((kt + 1) & 1, kt + 1);
            CP_COMMIT();
            CP_WAIT(1);
        } else {
            CP_WAIT(0);
        }
        __syncthreads();

        const uint32_t stAh = sbase + (kt & 1) * STAGE_B;
        const uint32_t stAl = stAh + SPLANE_B;
        const uint32_t stWh = stAh + 2 * SPLANE_B;
        const uint32_t stWl = stAh + 3 * SPLANE_B;

#pragma unroll
        for (int ks = 0; ks < 2; ks++) {
            const uint32_t ko = ks * 32;
            uint32_t ah[2][4], al[2][4];
            LDSM4(ah[0], stAh + aoff0 + ko);
            LDSM4(ah[1], stAh + aoff1 + ko);
            LDSM4(al[0], stAl + aoff0 + ko);
            LDSM4(al[1], stAl + aoff1 + ko);
            uint32_t bh[4][4], bl[4][4];
#pragma unroll
            for (int np = 0; np < 4; np++) {
                LDSM4(bh[np], stWh + boff[np] + ko);
                LDSM4(bl[np], stWl + boff[np] + ko);
            }
#pragma unroll
            for (int nt = 0; nt < 8; nt++) {
                const int np = nt >> 1, g = nt & 1;
                uint32_t bhf[2] = {bh[np][g], bh[np][2 + g]};
                uint32_t blf[2] = {bl[np][g], bl[np][2 + g]};
                mma_bf16(acc[0][nt], ah[0], blf);
                mma_bf16(acc[1][nt], ah[1], blf);
                mma_bf16(acc[0][nt], al[0], bhf);
                mma_bf16(acc[1][nt], al[1], bhf);
                mma_bf16(acc[0][nt], ah[0], bhf);
                mma_bf16(acc[1][nt], ah[1], bhf);
            }
        }
        __syncthreads();
    }

#pragma unroll
    for (int mt = 0; mt < 2; mt++) {
        const int r = m0 + wm * 32 + mt * 16 + rq;
#pragma unroll
        for (int nt = 0; nt < 8; nt++) {
            const int c = n0 + wn * 64 + nt * 8 + (wc << 1);
            *(float2*)&C[(size_t)r * N + c]       = make_float2(acc[mt][nt][0], acc[mt][nt][1]);
            *(float2*)&C[(size_t)(r + 8) * N + c] = make_float2(acc[mt][nt][2], acc[mt][nt][3]);
        }
    }
}

// ---------------------------------------------------------------------------
// Flash attention (causal, GQA), tf32 legacy mma — numerics identical to R8.
// 2 query heads per CTA share the K/V stream; Q/K/P fragments via ldmatrix
// (b16 8x8 matrix == 8x4 tf32 fragment), V via scalar LDS (layout transposed).
// ---------------------------------------------------------------------------
__device__ __forceinline__ uint32_t f2tf32(float v) {
    uint32_t r;
    asm("cvt.rna.tf32.f32 %0, %1;" : "=r"(r) : "f"(v));
    return r;
}
__device__ __forceinline__ void mma_tf32(float* d, const uint32_t* a, const uint32_t* b) {
    asm volatile(
        "mma.sync.aligned.m16n8k8.row.col.f32.tf32.tf32.f32 "
        "{%0,%1,%2,%3},{%4,%5,%6,%7},{%8,%9},{%0,%1,%2,%3};\n"
        : "+f"(d[0]), "+f"(d[1]), "+f"(d[2]), "+f"(d[3])
        : "r"(a[0]), "r"(a[1]), "r"(a[2]), "r"(a[3]), "r"(b[0]), "r"(b[1]));
}

#define QS 68   // == 4 (mod 32); LDSM rows -> banks {0,4,...,28}: conflict-free
#define VSs 72  // == 8 (mod 32)
// Qs[2 heads], Ps[2 heads], Ks, Vs
#define ATTN_SMEM ((2 * 64 * QS + 2 * 64 * QS + 64 * QS + 64 * VSs) * 4)

__global__ __launch_bounds__(256) void attn_kernel(
        const float* __restrict__ q, const float* __restrict__ kv,
        __nv_bfloat16* __restrict__ aohi, __nv_bfloat16* __restrict__ aolo) {
    extern __shared__ uint32_t sm[];
    uint32_t* QsAll = sm;                       // 2 * 64 * QS
    uint32_t* PsAll = QsAll + 2 * 64 * QS;      // 2 * 64 * QS
    uint32_t* Ks    = PsAll + 2 * 64 * QS;      // 64 * QS
    uint32_t* Vs    = Ks + 64 * QS;             // 64 * VSs

    const int tid  = threadIdx.x;
    const int lane = tid & 31;
    const int w    = tid >> 5;          // 0..7
    const int wg   = w >> 2;            // head sub-index 0/1
    const int wl   = w & 3;             // warp within head
    const int qb   = blockIdx.x;        // 64-row query block
    const int pidx = blockIdx.y;        // (b, head-pair)
    const int b    = pidx >> 4;
    const int hp   = pidx & 15;
    const int hq   = hp * 2 + wg;
    const int hkv  = hp >> 1;

    uint32_t* Qs = QsAll + wg * (64 * QS);
    uint32_t* Ps = PsAll + wg * (64 * QS);
    const uint32_t qsu = smem_u32(Qs);
    const uint32_t psu = smem_u32(Ps);
    const uint32_t ksu = smem_u32(Ks);

    // ---- Load both heads' Q tiles (threads 0-127 -> head 0, 128-255 -> head 1)
    {
        const int half  = tid >> 7;
        const int hrow  = (tid & 127) >> 4;
        const int hcol  = (tid & 15) << 2;
        const int hqh   = hp * 2 + half;
        uint32_t* Qdst  = QsAll + half * (64 * QS);
#pragma unroll
        for (int p = 0; p < 8; p++) {
            int row = p * 8 + hrow;
            const float4 v = *(const float4*)
                &q[((size_t)(b * kT + qb * 64 + row)) * kE + hqh * kHD + hcol];
            *(uint4*)&Qdst[row * QS + hcol] =
                make_uint4(f2tf32(v.x * 0.125f), f2tf32(v.y * 0.125f),
                           f2tf32(v.z * 0.125f), f2tf32(v.w * 0.125f));
        }
    }

    float mrow0 = -INFINITY, mrow1 = -INFINITY;
    float lrow0 = 0.f, lrow1 = 0.f;
    float o[8][4];
#pragma unroll
    for (int nt = 0; nt < 8; nt++)
#pragma unroll
        for (int i = 0; i < 4; i++) o[nt][i] = 0.f;

    const int rloc  = wl * 16 + (lane >> 2);   // warp's rows rloc, rloc+8 (0..63)
    const int ldrow = tid >> 4;
    const int ldcol = (tid & 15) << 2;

    // ldmatrix lane addresses (byte offsets; add k8*32 per step)
    const int lr8 = lane & 7;
    const int r8  = (lane >> 3) & 1;
    const int c4  = (lane >> 4) & 1;
    const uint32_t aoffQ = (uint32_t)((wl * 16 + lr8 + 8 * r8) * (QS * 4) + c4 * 16);
    uint32_t boffK[4];
#pragma unroll
    for (int np = 0; np < 4; np++)
        boffK[np] = (uint32_t)((np * 16 + lr8 + 8 * r8) * (QS * 4) + c4 * 16);

    for (int j = 0; j <= qb; j++) {
        // Fill shared K/V tile (64x64 each) once for both heads
#pragma unroll
        for (int p = 0; p < 4; p++) {
            int row = p * 16 + ldrow;
            size_t base = ((size_t)(b * kT + j * 64 + row)) * kKVN + hkv * kHD + ldcol;
            float4 kvr = *(const float4*)&kv[base];
            float4 vvr = *(const float4*)&kv[base + 512];
            *(uint4*)&Ks[row * QS + ldcol] =
                make_uint4(f2tf32(kvr.x), f2tf32(kvr.y), f2tf32(kvr.z), f2tf32(kvr.w));
            *(uint4*)&Vs[row * VSs + ldcol] =
                make_uint4(f2tf32(vvr.x), f2tf32(vvr.y), f2tf32(vvr.z), f2tf32(vvr.w));
        }
        __syncthreads();

        // S = Q * K^T (ldmatrix fragments)
        float s[8][4];
#pragma unroll
        for (int nt = 0; nt < 8; nt++) { s[nt][0] = s[nt][1] = s[nt][2] = s[nt][3] = 0.f; }

#pragma unroll
        for (int k8 = 0; k8 < 8; k8++) {
            const uint32_t ko = k8 * 32;
            uint32_t a[4];
            LDSM4(a, qsu + aoffQ + ko);
#pragma unroll
            for (int np = 0; np < 4; np++) {
                uint32_t kb[4];
                LDSM4(kb, ksu + boffK[np] + ko);
#pragma unroll
                for (int g = 0; g < 2; g++) {
                    uint32_t bb[2] = {kb[g], kb[2 + g]};
                    mma_tf32(s[2 * np + g], a, bb);
                }
            }
        }

        // Causal mask on the diagonal block
        if (j == qb) {
#pragma unroll
            for (int nt = 0; nt < 8; nt++) {
                int c0 = nt * 8 + ((lane & 3) << 1);
                if (c0     > rloc)     s[nt][0] = -INFINITY;
                if (c0 + 1 > rloc)     s[nt][1] = -INFINITY;
                if (c0     > rloc + 8) s[nt][2] = -INFINITY;
                if (c0 + 1 > rloc + 8) s[nt][3] = -INFINITY;
            }
        }

        // Online softmax
        float mx0 = -INFINITY, mx1 = -INFINITY;
#pragma unroll
        for (int nt = 0; nt < 8; nt++) {
            mx0 = fmaxf(mx0, fmaxf(s[nt][0], s[nt][1]));
            mx1 = fmaxf(mx1, fmaxf(s[nt][2], s[nt][3]));
        }
        mx0 = fmaxf(mx0, __shfl_xor_sync(0xffffffffu, mx0, 1));
        mx0 = fmaxf(mx0, __shfl_xor_sync(0xffffffffu, mx0, 2));
        mx1 = fmaxf(mx1, __shfl_xor_sync(0xffffffffu, mx1, 1));
        mx1 = fmaxf(mx1, __shfl_xor_sync(0xffffffffu, mx1, 2));

        float mnew0 = fmaxf(mrow0, mx0);
        float mnew1 = fmaxf(mrow1, mx1);
        float alpha0 = __expf(mrow0 - mnew0);
        float alpha1 = __expf(mrow1 - mnew1);
        mrow0 = mnew0; mrow1 = mnew1;

        float sum0 = 0.f, sum1 = 0.f;
#pragma unroll
        for (int nt = 0; nt < 8; nt++) {
            s[nt][0] = __expf(s[nt][0] - mnew0); sum0 += s[nt][0];
            s[nt][1] = __expf(s[nt][1] - mnew0); sum0 += s[nt][1];
            s[nt][2] = __expf(s[nt][2] - mnew1); sum1 += s[nt][2];
            s[nt][3] = __expf(s[nt][3] - mnew1); sum1 += s[nt][3];
        }
        sum0 += __shfl_xor_sync(0xffffffffu, sum0, 1);
        sum0 += __shfl_xor_sync(0xffffffffu, sum0, 2);
        sum1 += __shfl_xor_sync(0xffffffffu, sum1, 1);
        sum1 += __shfl_xor_sync(0xffffffffu, sum1, 2);

        lrow0 = lrow0 * alpha0 + sum0;
        lrow1 = lrow1 * alpha1 + sum1;

#pragma unroll
        for (int nt = 0; nt < 8; nt++) {
            o[nt][0] *= alpha0; o[nt][1] *= alpha0;
            o[nt][2] *= alpha1; o[nt][3] *= alpha1;
        }

        // C-frag -> A-frag via this head's Ps region (per-warp rows)
#pragma unroll
        for (int nt = 0; nt < 8; nt++) {
            int pc = nt * 8 + ((lane & 3) << 1);
            Ps[rloc * QS + pc]           = f2tf32(s[nt][0]);
            Ps[rloc * QS + pc + 1]       = f2tf32(s[nt][1]);
            Ps[(rloc + 8) * QS + pc]     = f2tf32(s[nt][2]);
            Ps[(rloc + 8) * QS + pc + 1] = f2tf32(s[nt][3]);
        }
        __syncwarp();

        // O += P * V  (P via ldmatrix; V via scalar LDS — transposed layout)
#pragma unroll
        for (int k8 = 0; k8 < 8; k8++) {
            const int kk = k8 * 8 + (lane & 3);
            uint32_t a[4];
            LDSM4(a, psu + aoffQ + k8 * 32);
#pragma unroll
            for (int nt = 0; nt < 8; nt++) {
                uint32_t bb[2];
                bb[0] = Vs[kk * VSs + nt * 8 + (lane >> 2)];
                bb[1] = Vs[(kk + 4) * VSs + nt * 8 + (lane >> 2)];
                mma_tf32(o[nt], a, bb);
            }
        }
        __syncthreads();   // all warps done reading Ks/Vs before next fill
    }

    // Normalize and emit bf16 hi/lo planes for the O-projection
    float inv0 = 1.f / lrow0;
    float inv1 = 1.f / lrow1;
    size_t r0 = (size_t)(b * kT + qb * 64 + rloc) * kE + hq * kHD;
    size_t r1 = (size_t)(b * kT + qb * 64 + rloc + 8) * kE + hq * kHD;
#pragma unroll
    for (int nt = 0; nt < 8; nt++) {
        int c = nt * 8 + ((lane & 3) << 1);
        float f00 = o[nt][0] * inv0, f01 = o[nt][1] * inv0;
        float f10 = o[nt][2] * inv1, f11 = o[nt][3] * inv1;
        __nv_bfloat16 h00, h01, h10, h11, l00, l01, l10, l11;
        splitbf(f00, h00, l00); splitbf(f01, h01, l01);
        splitbf(f10, h10, l10); splitbf(f11, h11, l11);
        *(__nv_bfloat162*)&aohi[r0 + c] = __nv_bfloat162(h00, h01);
        *(__nv_bfloat162*)&aolo[r0 + c] = __nv_bfloat162(l00, l01);
        *(__nv_bfloat162*)&aohi[r1 + c] = __nv_bfloat162(h10, h11);
        *(__nv_bfloat162*)&aolo[r1 + c] = __nv_bfloat162(l10, l11);
    }
}

// ---------------------------------------------------------------------------
// Launch
// ---------------------------------------------------------------------------
extern "C" void kernel_launch(void* const* d_in, const int* in_sizes, int n_in,
                              void* d_out, int out_size) {
    (void)in_sizes; (void)n_in; (void)out_size;
    const float* x   = (const float*)d_in[0];
    const float* Wq  = (const float*)d_in[1];
    const float* Wkv = (const float*)d_in[2];
    const float* Wo  = (const float*)d_in[3];
    float* out = (float*)d_out;

    float *q, *kvb;
    __nv_bfloat16 *xhi, *xlo, *wqhi, *wqlo, *wkvhi, *wkvlo, *wohi, *wolo, *aohi, *aolo;
    cudaGetSymbolAddress((void**)&q,     g_q);
    cudaGetSymbolAddress((void**)&kvb,   g_kv);
    cudaGetSymbolAddress((void**)&xhi,   g_xhi);
    cudaGetSymbolAddress((void**)&xlo,   g_xlo);
    cudaGetSymbolAddress((void**)&wqhi,  g_wqhi);
    cudaGetSymbolAddress((void**)&wqlo,  g_wqlo);
    cudaGetSymbolAddress((void**)&wkvhi, g_wkvhi);
    cudaGetSymbolAddress((void**)&wkvlo, g_wkvlo);
    cudaGetSymbolAddress((void**)&wohi,  g_wohi);
    cudaGetSymbolAddress((void**)&wolo,  g_wolo);
    cudaGetSymbolAddress((void**)&aohi,  g_aohi);
    cudaGetSymbolAddress((void**)&aolo,  g_aolo);

    cudaFuncSetAttribute(gemm_bf3,
                         cudaFuncAttributeMaxDynamicSharedMemorySize, GEMM_SMEM);
    cudaFuncSetAttribute(attn_kernel,
                         cudaFuncAttributeMaxDynamicSharedMemorySize, ATTN_SMEM);

    // Pre-split inputs to bf16 hi/lo planes
    const int nx   = kM * kE / 4,   nwq = kE * kE / 4;
    const int nwkv = kKVN * kE / 4, nwo = kE * kE / 4;
    split_kernel<<<(nx   + 255) / 256, 256>>>(x,   xhi,   xlo,   nx);
    split_kernel<<<(nwq  + 255) / 256, 256>>>(Wq,  wqhi,  wqlo,  nwq);
    split_kernel<<<(nwkv + 255) / 256, 256>>>(Wkv, wkvhi, wkvlo, nwkv);
    split_kernel<<<(nwo  + 255) / 256, 256>>>(Wo,  wohi,  wolo,  nwo);

    // Projections: bf16x3 on legacy tensor cores
    gemm_bf3<<<dim3(kE / 128,   kM / 128), 256, GEMM_SMEM>>>(xhi, xlo, wqhi,  wqlo,  q,   kE,   kE);
    gemm_bf3<<<dim3(kKVN / 128, kM / 128), 256, GEMM_SMEM>>>(xhi, xlo, wkvhi, wkvlo, kvb, kKVN, kE);

    // Attention: 2 query heads per CTA share one K/V stream
    attn_kernel<<<dim3(kT / 64, kB * kHQ / 2), 256, ATTN_SMEM>>>(q, kvb, aohi, aolo);

    // O-projection
    gemm_bf3<<<dim3(kE / 128,   kM / 128), 256, GEMM_SMEM>>>(aohi, aolo, wohi, wolo, out, kE, kE);
}

// round 10
// speedup vs baseline: 1.6329x; 1.4551x over previous
#include <cuda_runtime.h>
#include <cuda_fp16.h>
#include <math.h>
#include <stdint.h>

// Problem constants
#define kE   2048
#define kHQ  32
#define kHKV 8
#define kHD  64
#define kB   2
#define kT   2048
#define kM   (kB * kT)          // 4096 rows (B*T)
#define kKVN (2 * kHKV * kHD)   // 1024

// ---------------------------------------------------------------------------
// Device-global scratch (allocation-free per harness rules)
// ---------------------------------------------------------------------------
__device__ float g_q[kM * kE];       // q projection  (fp32)
__device__ float g_kv[kM * kKVN];    // kv projection (fp32): k [0,512), v [512,1024)
__device__ __half g_xh[kM * kE];                      // x, single fp16 plane
__device__ __half g_wqh[kE * kE],    g_wql[kE * kE];  // W hi/lo fp16 planes
__device__ __half g_wkvh[kKVN * kE], g_wkvl[kKVN * kE];
__device__ __half g_woh[kE * kE],    g_wol[kE * kE];
__device__ __half g_aoh[kM * kE];                     // attention out, fp16

// ---------------------------------------------------------------------------
// Helpers
// ---------------------------------------------------------------------------
__device__ __forceinline__ uint32_t smem_u32(const void* p) {
    uint32_t a;
    asm("{ .reg .u64 t; cvta.to.shared.u64 t, %1; cvt.u32.u64 %0, t; }"
        : "=r"(a) : "l"(p));
    return a;
}

__device__ __forceinline__ void cp16(uint32_t saddr, const void* g) {
    asm volatile("cp.async.cg.shared.global [%0], [%1], 16;"
                 :: "r"(saddr), "l"(g) : "memory");
}
#define CP_COMMIT()  asm volatile("cp.async.commit_group;" ::: "memory")
#define CP_WAIT(n)   asm volatile("cp.async.wait_group %0;" :: "n"(n) : "memory")

#define LDSM4(r, addr)                                                        \
    asm volatile("ldmatrix.sync.aligned.m8n8.x4.shared.b16 {%0,%1,%2,%3}, [%4];" \
        : "=r"((r)[0]), "=r"((r)[1]), "=r"((r)[2]), "=r"((r)[3]) : "r"(addr))

// fp16 tensor op: D(16x8,f32) += A(16x16,f16) * B(16x8,f16)
__device__ __forceinline__ void mma_fp16(float* d, const uint32_t* a, const uint32_t* b) {
    asm volatile(
        "mma.sync.aligned.m16n8k16.row.col.f32.f16.f16.f32 "
        "{%0,%1,%2,%3},{%4,%5,%6,%7},{%8,%9},{%0,%1,%2,%3};\n"
        : "+f"(d[0]), "+f"(d[1]), "+f"(d[2]), "+f"(d[3])
        : "r"(a[0]), "r"(a[1]), "r"(a[2]), "r"(a[3]), "r"(b[0]), "r"(b[1]));
}

__device__ __forceinline__ uint32_t pack_h2(float a, float b) {
    __half2 h = __floats2half2_rn(a, b);
    return *reinterpret_cast<uint32_t*>(&h);
}

// ---------------------------------------------------------------------------
// Split kernels
// ---------------------------------------------------------------------------
__global__ __launch_bounds__(256) void split1_kernel(
        const float* __restrict__ in, __half* __restrict__ hi, int n4) {
    int i = blockIdx.x * blockDim.x + threadIdx.x;
    if (i >= n4) return;
    float4 v = ((const float4*)in)[i];
    uint32_t* hp = (uint32_t*)hi;
    hp[2*i]   = pack_h2(v.x, v.y);
    hp[2*i+1] = pack_h2(v.z, v.w);
}

__global__ __launch_bounds__(256) void split2_kernel(
        const float* __restrict__ in, __half* __restrict__ hi,
        __half* __restrict__ lo, int n4) {
    int i = blockIdx.x * blockDim.x + threadIdx.x;
    if (i >= n4) return;
    float4 v = ((const float4*)in)[i];
    float hx = __half2float(__float2half_rn(v.x));
    float hy = __half2float(__float2half_rn(v.y));
    float hz = __half2float(__float2half_rn(v.z));
    float hw = __half2float(__float2half_rn(v.w));
    uint32_t* hp = (uint32_t*)hi;
    uint32_t* lp = (uint32_t*)lo;
    hp[2*i]   = pack_h2(v.x, v.y);
    hp[2*i+1] = pack_h2(v.z, v.w);
    lp[2*i]   = pack_h2(v.x - hx, v.y - hy);
    lp[2*i+1] = pack_h2(v.z - hz, v.w - hw);
}

// ---------------------------------------------------------------------------
// GEMM: C[M,N] = A[M,K] * W[N,K]^T, fp16 A-single / W-double (2 MMAs/elem-k16)
// CTA 128x128, K-tile 32, 8 warps, 2-stage cp.async, ldmatrix fragments.
// Planes: A-hi, W-hi, W-lo; 128 rows x 20-word stride (conflict-free LDSM).
// ---------------------------------------------------------------------------
#define SPLANE_W 2560                       // 128 * 20 u32 words
#define SPLANE_B (SPLANE_W * 4)             // 10240 bytes
#define STAGE_B  (3 * SPLANE_B)             // Ah, Wh, Wl
#define GEMM_SMEM (2 * STAGE_B)             // 61440 bytes

__global__ __launch_bounds__(256) void gemm_f16(
        const __half* __restrict__ Ah, const __half* __restrict__ Whi,
        const __half* __restrict__ Wlo,
        float* __restrict__ C, int N, int K) {
    extern __shared__ char smem[];
    const uint32_t sbase = smem_u32(smem);

    const int tid  = threadIdx.x;
    const int lane = tid & 31;
    const int wid  = tid >> 5;
    const int wm   = wid >> 1;        // 0..3
    const int wn   = wid & 1;         // 0..1
    const int m0   = blockIdx.y * 128;
    const int n0   = blockIdx.x * 128;

    float acc[2][8][4];
#pragma unroll
    for (int i = 0; i < 2; i++)
#pragma unroll
        for (int j = 0; j < 8; j++)
#pragma unroll
            for (int k = 0; k < 4; k++) acc[i][j][k] = 0.f;

    const size_t gs = (size_t)K * 2;  // bytes per global row
    const int crow  = tid >> 1;       // 0..127
    const int cbo   = (tid & 1) << 5; // 0 or 32 bytes

    const char* pA  = (const char*)Ah;
    const char* pWh = (const char*)Whi;
    const char* pWl = (const char*)Wlo;

    const int NKT = K >> 5;

    auto copy_tile = [&](int s, int kt) {
        const uint32_t st = sbase + s * STAGE_B + crow * 80 + cbo;
        const size_t goA = (size_t)(m0 + crow) * gs + (size_t)kt * 64 + cbo;
        const size_t goW = (size_t)(n0 + crow) * gs + (size_t)kt * 64 + cbo;
        cp16(st,                      pA  + goA);
        cp16(st + 16,                 pA  + goA + 16);
        cp16(st + SPLANE_B,           pWh + goW);
        cp16(st + SPLANE_B + 16,      pWh + goW + 16);
        cp16(st + 2 * SPLANE_B,       pWl + goW);
        cp16(st + 2 * SPLANE_B + 16,  pWl + goW + 16);
    };

    copy_tile(0, 0);
    CP_COMMIT();

    // ldmatrix lane-address components
    const int lr8 = lane & 7;
    const int r8  = (lane >> 3) & 1;
    const int c4  = (lane >> 4) & 1;
    const uint32_t aoff0 = (uint32_t)((wm * 32 + lr8 + 8 * r8) * 80 + c4 * 16);
    const uint32_t aoff1 = aoff0 + 16 * 80;
    uint32_t boff[4];
#pragma unroll
    for (int np = 0; np < 4; np++)
        boff[np] = (uint32_t)((wn * 64 + np * 16 + lr8 + 8 * r8) * 80 + c4 * 16);

    const int rq = lane >> 2;
    const int wc = lane & 3;

    for (int kt = 0; kt < NKT; kt++) {
        if (kt + 1 < NKT) {
            copy_tile((kt + 1) & 1, kt + 1);
            CP_COMMIT();
            CP_WAIT(1);
        } else {
            CP_WAIT(0);
        }
        __syncthreads();

        const uint32_t stAh = sbase + (kt & 1) * STAGE_B;
        const uint32_t stWh = stAh + SPLANE_B;
        const uint32_t stWl = stAh + 2 * SPLANE_B;

#pragma unroll
        for (int ks = 0; ks < 2; ks++) {
            const uint32_t ko = ks * 32;
            uint32_t ah[2][4];
            LDSM4(ah[0], stAh + aoff0 + ko);
            LDSM4(ah[1], stAh + aoff1 + ko);
            uint32_t bh[4][4], bl[4][4];
#pragma unroll
            for (int np = 0; np < 4; np++) {
                LDSM4(bh[np], stWh + boff[np] + ko);
                LDSM4(bl[np], stWl + boff[np] + ko);
            }
            // pass 1: A*Whi (16 independent MMAs)
#pragma unroll
            for (int nt = 0; nt < 8; nt++) {
                const int np = nt >> 1, g = nt & 1;
                uint32_t bhf[2] = {bh[np][g], bh[np][2 + g]};
                mma_fp16(acc[0][nt], ah[0], bhf);
                mma_fp16(acc[1][nt], ah[1], bhf);
            }
            // pass 2: A*Wlo
#pragma unroll
            for (int nt = 0; nt < 8; nt++) {
                const int np = nt >> 1, g = nt & 1;
                uint32_t blf[2] = {bl[np][g], bl[np][2 + g]};
                mma_fp16(acc[0][nt], ah[0], blf);
                mma_fp16(acc[1][nt], ah[1], blf);
            }
        }
        __syncthreads();
    }

#pragma unroll
    for (int mt = 0; mt < 2; mt++) {
        const int r = m0 + wm * 32 + mt * 16 + rq;
#pragma unroll
        for (int nt = 0; nt < 8; nt++) {
            const int c = n0 + wn * 64 + nt * 8 + (wc << 1);
            *(float2*)&C[(size_t)r * N + c]       = make_float2(acc[mt][nt][0], acc[mt][nt][1]);
            *(float2*)&C[(size_t)(r + 8) * N + c] = make_float2(acc[mt][nt][2], acc[mt][nt][3]);
        }
    }
}

// ---------------------------------------------------------------------------
// Flash attention (causal, GQA), fp16 m16n8k16 (same 10-bit mantissa as tf32).
// 2 query heads per CTA share the K/V stream. Q/K/P via ldmatrix; V packed
// as half2 (k,k+1) pairs at fill time -> single LDS.32 per B register.
// ---------------------------------------------------------------------------
// smem byte layout (all row strides 144B = 72 halfwords, Vp 288B = 72 words)
#define AQ_OFF 0          // Qs: 2 heads * 64 rows * 144B = 18432
#define AP_OFF 18432      // Ps: 2 heads * 64 * 144      = 18432
#define AK_OFF 36864      // Ks: 64 * 144                = 9216
#define AV_OFF 46080      // Vp: 32 * 288                = 9216
#define ATTN_SMEM 55296

__global__ __launch_bounds__(256) void attn_kernel(
        const float* __restrict__ q, const float* __restrict__ kv,
        __half* __restrict__ aoh) {
    extern __shared__ char smc[];
    const uint32_t sb = smem_u32(smc);

    const int tid  = threadIdx.x;
    const int lane = tid & 31;
    const int w    = tid >> 5;          // 0..7
    const int wg   = w >> 2;            // head sub-index 0/1
    const int wl   = w & 3;             // warp within head
    const int qb   = blockIdx.x;        // 64-row query block
    const int pidx = blockIdx.y;        // (b, head-pair)
    const int b    = pidx >> 4;
    const int hp   = pidx & 15;
    const int hq   = hp * 2 + wg;
    const int hkv  = hp >> 1;

    const uint32_t qsu = sb + AQ_OFF + wg * 9216;
    const uint32_t psu = sb + AP_OFF + wg * 9216;
    const uint32_t ksu = sb + AK_OFF;
    uint32_t* Vw = (uint32_t*)(smc + AV_OFF);

    // ---- Load both heads' Q tiles (halves of the CTA), scaled, fp16
    {
        const int half  = tid >> 7;
        const int hrow  = (tid & 127) >> 4;       // 0..7
        const int hcol  = (tid & 15) << 2;        // 0..60
        const int hqh   = hp * 2 + half;
        char* Qdst = smc + AQ_OFF + half * 9216;
#pragma unroll
        for (int p = 0; p < 8; p++) {
            int row = p * 8 + hrow;
            const float4 v = *(const float4*)
                &q[((size_t)(b * kT + qb * 64 + row)) * kE + hqh * kHD + hcol];
            uint2 pk;
            pk.x = pack_h2(v.x * 0.125f, v.y * 0.125f);
            pk.y = pack_h2(v.z * 0.125f, v.w * 0.125f);
            *(uint2*)(Qdst + row * 144 + hcol * 2) = pk;
        }
    }

    float mrow0 = -INFINITY, mrow1 = -INFINITY;
    float lrow0 = 0.f, lrow1 = 0.f;
    float o[8][4];
#pragma unroll
    for (int nt = 0; nt < 8; nt++)
#pragma unroll
        for (int i = 0; i < 4; i++) o[nt][i] = 0.f;

    const int rloc  = wl * 16 + (lane >> 2);   // warp's rows rloc, rloc+8 (0..63)
    const int ldrow = tid >> 4;                // 0..15
    const int ldcol = (tid & 15) << 2;         // 0..60

    // ldmatrix lane addresses (byte offsets; +32 per k16 step)
    const int lr8 = lane & 7;
    const int r8  = (lane >> 3) & 1;
    const int c4  = (lane >> 4) & 1;
    const uint32_t aoffQ = (uint32_t)((wl * 16 + lr8 + 8 * r8) * 144 + c4 * 16);
    uint32_t boffK[4];
#pragma unroll
    for (int np = 0; np < 4; np++)
        boffK[np] = (uint32_t)((np * 16 + lr8 + 8 * r8) * 144 + c4 * 16);

    const int la = lane & 3;
    const int nq = lane >> 2;

    for (int j = 0; j <= qb; j++) {
        // Fill shared K (fp16 [n][k]) and V (half2 pairs [k/2][n]) tiles
#pragma unroll
        for (int p = 0; p < 4; p++) {
            int row = p * 16 + ldrow;
            size_t base = ((size_t)(b * kT + j * 64 + row)) * kKVN + hkv * kHD + ldcol;
            float4 kvr = *(const float4*)&kv[base];
            uint2 pk;
            pk.x = pack_h2(kvr.x, kvr.y);
            pk.y = pack_h2(kvr.z, kvr.w);
            *(uint2*)(smc + AK_OFF + row * 144 + ldcol * 2) = pk;
        }
#pragma unroll
        for (int p = 0; p < 2; p++) {
            int k2 = p * 16 + ldrow;                 // 0..31 (pair of t-rows)
            size_t ba = ((size_t)(b * kT + j * 64 + 2 * k2)) * kKVN + hkv * kHD + 512 + ldcol;
            float4 va = *(const float4*)&kv[ba];
            float4 vb = *(const float4*)&kv[ba + kKVN];
            uint4 pk;
            pk.x = pack_h2(va.x, vb.x);
            pk.y = pack_h2(va.y, vb.y);
            pk.z = pack_h2(va.z, vb.z);
            pk.w = pack_h2(va.w, vb.w);
            *(uint4*)(smc + AV_OFF + k2 * 288 + ldcol * 4) = pk;
        }
        __syncthreads();

        // S = Q * K^T  (fp16 m16n8k16, 4 k-steps)
        float s[8][4];
#pragma unroll
        for (int nt = 0; nt < 8; nt++) { s[nt][0] = s[nt][1] = s[nt][2] = s[nt][3] = 0.f; }

#pragma unroll
        for (int ks = 0; ks < 4; ks++) {
            const uint32_t ko = ks * 32;
            uint32_t a[4];
            LDSM4(a, qsu + aoffQ + ko);
#pragma unroll
            for (int np = 0; np < 4; np++) {
                uint32_t kb[4];
                LDSM4(kb, ksu + boffK[np] + ko);
#pragma unroll
                for (int g = 0; g < 2; g++) {
                    uint32_t bb[2] = {kb[g], kb[2 + g]};
                    mma_fp16(s[2 * np + g], a, bb);
                }
            }
        }

        // Causal mask on the diagonal block
        if (j == qb) {
#pragma unroll
            for (int nt = 0; nt < 8; nt++) {
                int c0 = nt * 8 + (la << 1);
                if (c0     > rloc)     s[nt][0] = -INFINITY;
                if (c0 + 1 > rloc)     s[nt][1] = -INFINITY;
                if (c0     > rloc + 8) s[nt][2] = -INFINITY;
                if (c0 + 1 > rloc + 8) s[nt][3] = -INFINITY;
            }
        }

        // Online softmax
        float mx0 = -INFINITY, mx1 = -INFINITY;
#pragma unroll
        for (int nt = 0; nt < 8; nt++) {
            mx0 = fmaxf(mx0, fmaxf(s[nt][0], s[nt][1]));
            mx1 = fmaxf(mx1, fmaxf(s[nt][2], s[nt][3]));
        }
        mx0 = fmaxf(mx0, __shfl_xor_sync(0xffffffffu, mx0, 1));
        mx0 = fmaxf(mx0, __shfl_xor_sync(0xffffffffu, mx0, 2));
        mx1 = fmaxf(mx1, __shfl_xor_sync(0xffffffffu, mx1, 1));
        mx1 = fmaxf(mx1, __shfl_xor_sync(0xffffffffu, mx1, 2));

        float mnew0 = fmaxf(mrow0, mx0);
        float mnew1 = fmaxf(mrow1, mx1);
        float alpha0 = __expf(mrow0 - mnew0);
        float alpha1 = __expf(mrow1 - mnew1);
        mrow0 = mnew0; mrow1 = mnew1;

        float sum0 = 0.f, sum1 = 0.f;
#pragma unroll
        for (int nt = 0; nt < 8; nt++) {
            s[nt][0] = __expf(s[nt][0] - mnew0); sum0 += s[nt][0];
            s[nt][1] = __expf(s[nt][1] - mnew0); sum0 += s[nt][1];
            s[nt][2] = __expf(s[nt][2] - mnew1); sum1 += s[nt][2];
            s[nt][3] = __expf(s[nt][3] - mnew1); sum1 += s[nt][3];
        }
        sum0 += __shfl_xor_sync(0xffffffffu, sum0, 1);
        sum0 += __shfl_xor_sync(0xffffffffu, sum0, 2);
        sum1 += __shfl_xor_sync(0xffffffffu, sum1, 1);
        sum1 += __shfl_xor_sync(0xffffffffu, sum1, 2);

        lrow0 = lrow0 * alpha0 + sum0;
        lrow1 = lrow1 * alpha1 + sum1;

#pragma unroll
        for (int nt = 0; nt < 8; nt++) {
            o[nt][0] *= alpha0; o[nt][1] *= alpha0;
            o[nt][2] *= alpha1; o[nt][3] *= alpha1;
        }

        // C-frag -> A-frag: store P as fp16 pairs (one 32-bit STS per pair)
#pragma unroll
        for (int nt = 0; nt < 8; nt++) {
            int pc = nt * 8 + (la << 1);
            *(uint32_t*)(smc + AP_OFF + wg * 9216 + rloc * 144 + pc * 2) =
                pack_h2(s[nt][0], s[nt][1]);
            *(uint32_t*)(smc + AP_OFF + wg * 9216 + (rloc + 8) * 144 + pc * 2) =
                pack_h2(s[nt][2], s[nt][3]);
        }
        __syncwarp();

        // O += P * V (P via ldmatrix, V pairs via LDS.32)
#pragma unroll
        for (int ks = 0; ks < 4; ks++) {
            uint32_t a[4];
            LDSM4(a, psu + aoffQ + ks * 32);
#pragma unroll
            for (int nt = 0; nt < 8; nt++) {
                const int n = nt * 8 + nq;
                uint32_t bb[2];
                bb[0] = Vw[(ks * 8 + la) * 72 + n];
                bb[1] = Vw[(ks * 8 + la + 4) * 72 + n];
                mma_fp16(o[nt], a, bb);
            }
        }
        __syncthreads();   // all warps done with Ks/Vs before next fill
    }

    // Normalize and emit single fp16 plane for the O-projection
    float inv0 = 1.f / lrow0;
    float inv1 = 1.f / lrow1;
    size_t r0 = (size_t)(b * kT + qb * 64 + rloc) * kE + hq * kHD;
    size_t r1 = (size_t)(b * kT + qb * 64 + rloc + 8) * kE + hq * kHD;
#pragma unroll
    for (int nt = 0; nt < 8; nt++) {
        int c = nt * 8 + (la << 1);
        *(uint32_t*)&aoh[r0 + c] = pack_h2(o[nt][0] * inv0, o[nt][1] * inv0);
        *(uint32_t*)&aoh[r1 + c] = pack_h2(o[nt][2] * inv1, o[nt][3] * inv1);
    }
}

// ---------------------------------------------------------------------------
// Launch
// ---------------------------------------------------------------------------
extern "C" void kernel_launch(void* const* d_in, const int* in_sizes, int n_in,
                              void* d_out, int out_size) {
    (void)in_sizes; (void)n_in; (void)out_size;
    const float* x   = (const float*)d_in[0];
    const float* Wq  = (const float*)d_in[1];
    const float* Wkv = (const float*)d_in[2];
    const float* Wo  = (const float*)d_in[3];
    float* out = (float*)d_out;

    float *q, *kvb;
    __half *xh, *wqh, *wql, *wkvh, *wkvl, *woh, *wol, *aoh;
    cudaGetSymbolAddress((void**)&q,    g_q);
    cudaGetSymbolAddress((void**)&kvb,  g_kv);
    cudaGetSymbolAddress((void**)&xh,   g_xh);
    cudaGetSymbolAddress((void**)&wqh,  g_wqh);
    cudaGetSymbolAddress((void**)&wql,  g_wql);
    cudaGetSymbolAddress((void**)&wkvh, g_wkvh);
    cudaGetSymbolAddress((void**)&wkvl, g_wkvl);
    cudaGetSymbolAddress((void**)&woh,  g_woh);
    cudaGetSymbolAddress((void**)&wol,  g_wol);
    cudaGetSymbolAddress((void**)&aoh,  g_aoh);

    cudaFuncSetAttribute(gemm_f16,
                         cudaFuncAttributeMaxDynamicSharedMemorySize, GEMM_SMEM);
    cudaFuncSetAttribute(attn_kernel,
                         cudaFuncAttributeMaxDynamicSharedMemorySize, ATTN_SMEM);

    // Splits: x -> single fp16 plane; weights -> fp16 hi+lo
    const int nx   = kM * kE / 4,   nwq = kE * kE / 4;
    const int nwkv = kKVN * kE / 4, nwo = kE * kE / 4;
    split1_kernel<<<(nx   + 255) / 256, 256>>>(x,   xh,   nx);
    split2_kernel<<<(nwq  + 255) / 256, 256>>>(Wq,  wqh,  wql,  nwq);
    split2_kernel<<<(nwkv + 255) / 256, 256>>>(Wkv, wkvh, wkvl, nwkv);
    split2_kernel<<<(nwo  + 255) / 256, 256>>>(Wo,  woh,  wol,  nwo);

    // Projections: fp16 A-single / W-double (2 MMAs per k16)
    gemm_f16<<<dim3(kE / 128,   kM / 128), 256, GEMM_SMEM>>>(xh, wqh,  wql,  q,   kE,   kE);
    gemm_f16<<<dim3(kKVN / 128, kM / 128), 256, GEMM_SMEM>>>(xh, wkvh, wkvl, kvb, kKVN, kE);

    // Attention: fp16 m16n8k16, 2 query heads per CTA share one K/V stream
    attn_kernel<<<dim3(kT / 64, kB * kHQ / 2), 256, ATTN_SMEM>>>(q, kvb, aoh);

    // O-projection
    gemm_f16<<<dim3(kE / 128,   kM / 128), 256, GEMM_SMEM>>>(aoh, woh, wol, out, kE, kE);
}

// round 11
// speedup vs baseline: 2.3131x; 1.4166x over previous
#include <cuda_runtime.h>
#include <cuda_fp16.h>
#include <math.h>
#include <stdint.h>

// Problem constants
#define kE   2048
#define kHQ  32
#define kHKV 8
#define kHD  64
#define kB   2
#define kT   2048
#define kM   (kB * kT)          // 4096 rows (B*T)
#define kKVN (2 * kHKV * kHD)   // 1024

// ---------------------------------------------------------------------------
// Device-global scratch (allocation-free per harness rules)
// ---------------------------------------------------------------------------
__device__ float g_q[kM * kE];       // q projection  (fp32)
__device__ float g_kv[kM * kKVN];    // kv projection (fp32): k [0,512), v [512,1024)
__device__ __half g_xh[kM * kE];                      // x, fp16
__device__ __half g_wqh[kE * kE];                     // weights, fp16 single plane
__device__ __half g_wkvh[kKVN * kE];
__device__ __half g_woh[kE * kE];
__device__ __half g_aoh[kM * kE];                     // attention out, fp16

// ---------------------------------------------------------------------------
// Helpers
// ---------------------------------------------------------------------------
__device__ __forceinline__ uint32_t smem_u32(const void* p) {
    uint32_t a;
    asm("{ .reg .u64 t; cvta.to.shared.u64 t, %1; cvt.u32.u64 %0, t; }"
        : "=r"(a) : "l"(p));
    return a;
}

__device__ __forceinline__ void cp16(uint32_t saddr, const void* g) {
    asm volatile("cp.async.cg.shared.global [%0], [%1], 16;"
                 :: "r"(saddr), "l"(g) : "memory");
}
#define CP_COMMIT()  asm volatile("cp.async.commit_group;" ::: "memory")
#define CP_WAIT(n)   asm volatile("cp.async.wait_group %0;" :: "n"(n) : "memory")

#define LDSM4(r, addr)                                                        \
    asm volatile("ldmatrix.sync.aligned.m8n8.x4.shared.b16 {%0,%1,%2,%3}, [%4];" \
        : "=r"((r)[0]), "=r"((r)[1]), "=r"((r)[2]), "=r"((r)[3]) : "r"(addr))

// fp16 tensor op: D(16x8,f32) += A(16x16,f16) * B(16x8,f16)
__device__ __forceinline__ void mma_fp16(float* d, const uint32_t* a, const uint32_t* b) {
    asm volatile(
        "mma.sync.aligned.m16n8k16.row.col.f32.f16.f16.f32 "
        "{%0,%1,%2,%3},{%4,%5,%6,%7},{%8,%9},{%0,%1,%2,%3};\n"
        : "+f"(d[0]), "+f"(d[1]), "+f"(d[2]), "+f"(d[3])
        : "r"(a[0]), "r"(a[1]), "r"(a[2]), "r"(a[3]), "r"(b[0]), "r"(b[1]));
}

__device__ __forceinline__ uint32_t pack_h2(float a, float b) {
    __half2 h = __floats2half2_rn(a, b);
    return *reinterpret_cast<uint32_t*>(&h);
}

// fp32 -> fp16 cast kernel
__global__ __launch_bounds__(256) void split1_kernel(
        const float* __restrict__ in, __half* __restrict__ hi, int n4) {
    int i = blockIdx.x * blockDim.x + threadIdx.x;
    if (i >= n4) return;
    float4 v = ((const float4*)in)[i];
    uint32_t* hp = (uint32_t*)hi;
    hp[2*i]   = pack_h2(v.x, v.y);
    hp[2*i+1] = pack_h2(v.z, v.w);
}

// ---------------------------------------------------------------------------
// GEMM: C[M,N] = A[M,K] * W[N,K]^T, plain fp16 (1 MMA per k16).
// CTA 128x128, K-tile 32, 8 warps, 2-stage cp.async, ldmatrix fragments.
// Planes: A, W; 128 rows x 20-word stride (conflict-free LDSM).
// ---------------------------------------------------------------------------
#define SPLANE_W 2560                       // 128 * 20 u32 words
#define SPLANE_B (SPLANE_W * 4)             // 10240 bytes
#define STAGE_B  (2 * SPLANE_B)             // A, W
#define GEMM_SMEM (2 * STAGE_B)             // 40960 bytes

__global__ __launch_bounds__(256) void gemm_f16(
        const __half* __restrict__ Ah, const __half* __restrict__ Whi,
        float* __restrict__ C, int N, int K) {
    extern __shared__ char smem[];
    const uint32_t sbase = smem_u32(smem);

    const int tid  = threadIdx.x;
    const int lane = tid & 31;
    const int wid  = tid >> 5;
    const int wm   = wid >> 1;        // 0..3
    const int wn   = wid & 1;         // 0..1
    const int m0   = blockIdx.y * 128;
    const int n0   = blockIdx.x * 128;

    float acc[2][8][4];
#pragma unroll
    for (int i = 0; i < 2; i++)
#pragma unroll
        for (int j = 0; j < 8; j++)
#pragma unroll
            for (int k = 0; k < 4; k++) acc[i][j][k] = 0.f;

    const size_t gs = (size_t)K * 2;  // bytes per global row
    const int crow  = tid >> 1;       // 0..127
    const int cbo   = (tid & 1) << 5; // 0 or 32 bytes

    const char* pA = (const char*)Ah;
    const char* pW = (const char*)Whi;

    const int NKT = K >> 5;

    auto copy_tile = [&](int s, int kt) {
        const uint32_t st = sbase + s * STAGE_B + crow * 80 + cbo;
        const size_t goA = (size_t)(m0 + crow) * gs + (size_t)kt * 64 + cbo;
        const size_t goW = (size_t)(n0 + crow) * gs + (size_t)kt * 64 + cbo;
        cp16(st,                 pA + goA);
        cp16(st + 16,            pA + goA + 16);
        cp16(st + SPLANE_B,      pW + goW);
        cp16(st + SPLANE_B + 16, pW + goW + 16);
    };

    copy_tile(0, 0);
    CP_COMMIT();

    // ldmatrix lane-address components
    const int lr8 = lane & 7;
    const int r8  = (lane >> 3) & 1;
    const int c4  = (lane >> 4) & 1;
    const uint32_t aoff0 = (uint32_t)((wm * 32 + lr8 + 8 * r8) * 80 + c4 * 16);
    const uint32_t aoff1 = aoff0 + 16 * 80;
    uint32_t boff[4];
#pragma unroll
    for (int np = 0; np < 4; np++)
        boff[np] = (uint32_t)((wn * 64 + np * 16 + lr8 + 8 * r8) * 80 + c4 * 16);

    const int rq = lane >> 2;
    const int wc = lane & 3;

    for (int kt = 0; kt < NKT; kt++) {
        if (kt + 1 < NKT) {
            copy_tile((kt + 1) & 1, kt + 1);
            CP_COMMIT();
            CP_WAIT(1);
        } else {
            CP_WAIT(0);
        }
        __syncthreads();

        const uint32_t stA = sbase + (kt & 1) * STAGE_B;
        const uint32_t stW = stA + SPLANE_B;

#pragma unroll
        for (int ks = 0; ks < 2; ks++) {
            const uint32_t ko = ks * 32;
            uint32_t ah[2][4];
            LDSM4(ah[0], stA + aoff0 + ko);
            LDSM4(ah[1], stA + aoff1 + ko);
            uint32_t bh[4][4];
#pragma unroll
            for (int np = 0; np < 4; np++)
                LDSM4(bh[np], stW + boff[np] + ko);
#pragma unroll
            for (int nt = 0; nt < 8; nt++) {
                const int np = nt >> 1, g = nt & 1;
                uint32_t bhf[2] = {bh[np][g], bh[np][2 + g]};
                mma_fp16(acc[0][nt], ah[0], bhf);
                mma_fp16(acc[1][nt], ah[1], bhf);
            }
        }
        __syncthreads();
    }

#pragma unroll
    for (int mt = 0; mt < 2; mt++) {
        const int r = m0 + wm * 32 + mt * 16 + rq;
#pragma unroll
        for (int nt = 0; nt < 8; nt++) {
            const int c = n0 + wn * 64 + nt * 8 + (wc << 1);
            *(float2*)&C[(size_t)r * N + c]       = make_float2(acc[mt][nt][0], acc[mt][nt][1]);
            *(float2*)&C[(size_t)(r + 8) * N + c] = make_float2(acc[mt][nt][2], acc[mt][nt][3]);
        }
    }
}

// ---------------------------------------------------------------------------
// Flash attention (causal, GQA), fp16 m16n8k16 — unchanged from R10.
// 2 query heads per CTA share the K/V stream. Q/K/P via ldmatrix; V packed
// as half2 (k,k+1) pairs at fill time -> single LDS.32 per B register.
// ---------------------------------------------------------------------------
#define AQ_OFF 0          // Qs: 2 heads * 64 rows * 144B = 18432
#define AP_OFF 18432      // Ps: 2 heads * 64 * 144      = 18432
#define AK_OFF 36864      // Ks: 64 * 144                = 9216
#define AV_OFF 46080      // Vp: 32 * 288                = 9216
#define ATTN_SMEM 55296

__global__ __launch_bounds__(256) void attn_kernel(
        const float* __restrict__ q, const float* __restrict__ kv,
        __half* __restrict__ aoh) {
    extern __shared__ char smc[];
    const uint32_t sb = smem_u32(smc);

    const int tid  = threadIdx.x;
    const int lane = tid & 31;
    const int w    = tid >> 5;          // 0..7
    const int wg   = w >> 2;            // head sub-index 0/1
    const int wl   = w & 3;             // warp within head
    const int qb   = blockIdx.x;        // 64-row query block
    const int pidx = blockIdx.y;        // (b, head-pair)
    const int b    = pidx >> 4;
    const int hp   = pidx & 15;
    const int hq   = hp * 2 + wg;
    const int hkv  = hp >> 1;

    const uint32_t qsu = sb + AQ_OFF + wg * 9216;
    const uint32_t psu = sb + AP_OFF + wg * 9216;
    const uint32_t ksu = sb + AK_OFF;
    uint32_t* Vw = (uint32_t*)(smc + AV_OFF);

    // ---- Load both heads' Q tiles (halves of the CTA), scaled, fp16
    {
        const int half  = tid >> 7;
        const int hrow  = (tid & 127) >> 4;       // 0..7
        const int hcol  = (tid & 15) << 2;        // 0..60
        const int hqh   = hp * 2 + half;
        char* Qdst = smc + AQ_OFF + half * 9216;
#pragma unroll
        for (int p = 0; p < 8; p++) {
            int row = p * 8 + hrow;
            const float4 v = *(const float4*)
                &q[((size_t)(b * kT + qb * 64 + row)) * kE + hqh * kHD + hcol];
            uint2 pk;
            pk.x = pack_h2(v.x * 0.125f, v.y * 0.125f);
            pk.y = pack_h2(v.z * 0.125f, v.w * 0.125f);
            *(uint2*)(Qdst + row * 144 + hcol * 2) = pk;
        }
    }

    float mrow0 = -INFINITY, mrow1 = -INFINITY;
    float lrow0 = 0.f, lrow1 = 0.f;
    float o[8][4];
#pragma unroll
    for (int nt = 0; nt < 8; nt++)
#pragma unroll
        for (int i = 0; i < 4; i++) o[nt][i] = 0.f;

    const int rloc  = wl * 16 + (lane >> 2);   // warp's rows rloc, rloc+8 (0..63)
    const int ldrow = tid >> 4;                // 0..15
    const int ldcol = (tid & 15) << 2;         // 0..60

    // ldmatrix lane addresses (byte offsets; +32 per k16 step)
    const int lr8 = lane & 7;
    const int r8  = (lane >> 3) & 1;
    const int c4  = (lane >> 4) & 1;
    const uint32_t aoffQ = (uint32_t)((wl * 16 + lr8 + 8 * r8) * 144 + c4 * 16);
    uint32_t boffK[4];
#pragma unroll
    for (int np = 0; np < 4; np++)
        boffK[np] = (uint32_t)((np * 16 + lr8 + 8 * r8) * 144 + c4 * 16);

    const int la = lane & 3;
    const int nq = lane >> 2;

    for (int j = 0; j <= qb; j++) {
        // Fill shared K (fp16 [n][k]) and V (half2 pairs [k/2][n]) tiles
#pragma unroll
        for (int p = 0; p < 4; p++) {
            int row = p * 16 + ldrow;
            size_t base = ((size_t)(b * kT + j * 64 + row)) * kKVN + hkv * kHD + ldcol;
            float4 kvr = *(const float4*)&kv[base];
            uint2 pk;
            pk.x = pack_h2(kvr.x, kvr.y);
            pk.y = pack_h2(kvr.z, kvr.w);
            *(uint2*)(smc + AK_OFF + row * 144 + ldcol * 2) = pk;
        }
#pragma unroll
        for (int p = 0; p < 2; p++) {
            int k2 = p * 16 + ldrow;                 // 0..31 (pair of t-rows)
            size_t ba = ((size_t)(b * kT + j * 64 + 2 * k2)) * kKVN + hkv * kHD + 512 + ldcol;
            float4 va = *(const float4*)&kv[ba];
            float4 vb = *(const float4*)&kv[ba + kKVN];
            uint4 pk;
            pk.x = pack_h2(va.x, vb.x);
            pk.y = pack_h2(va.y, vb.y);
            pk.z = pack_h2(va.z, vb.z);
            pk.w = pack_h2(va.w, vb.w);
            *(uint4*)(smc + AV_OFF + k2 * 288 + ldcol * 4) = pk;
        }
        __syncthreads();

        // S = Q * K^T  (fp16 m16n8k16, 4 k-steps)
        float s[8][4];
#pragma unroll
        for (int nt = 0; nt < 8; nt++) { s[nt][0] = s[nt][1] = s[nt][2] = s[nt][3] = 0.f; }

#pragma unroll
        for (int ks = 0; ks < 4; ks++) {
            const uint32_t ko = ks * 32;
            uint32_t a[4];
            LDSM4(a, qsu + aoffQ + ko);
#pragma unroll
            for (int np = 0; np < 4; np++) {
                uint32_t kb[4];
                LDSM4(kb, ksu + boffK[np] + ko);
#pragma unroll
                for (int g = 0; g < 2; g++) {
                    uint32_t bb[2] = {kb[g], kb[2 + g]};
                    mma_fp16(s[2 * np + g], a, bb);
                }
            }
        }

        // Causal mask on the diagonal block
        if (j == qb) {
#pragma unroll
            for (int nt = 0; nt < 8; nt++) {
                int c0 = nt * 8 + (la << 1);
                if (c0     > rloc)     s[nt][0] = -INFINITY;
                if (c0 + 1 > rloc)     s[nt][1] = -INFINITY;
                if (c0     > rloc + 8) s[nt][2] = -INFINITY;
                if (c0 + 1 > rloc + 8) s[nt][3] = -INFINITY;
            }
        }

        // Online softmax
        float mx0 = -INFINITY, mx1 = -INFINITY;
#pragma unroll
        for (int nt = 0; nt < 8; nt++) {
            mx0 = fmaxf(mx0, fmaxf(s[nt][0], s[nt][1]));
            mx1 = fmaxf(mx1, fmaxf(s[nt][2], s[nt][3]));
        }
        mx0 = fmaxf(mx0, __shfl_xor_sync(0xffffffffu, mx0, 1));
        mx0 = fmaxf(mx0, __shfl_xor_sync(0xffffffffu, mx0, 2));
        mx1 = fmaxf(mx1, __shfl_xor_sync(0xffffffffu, mx1, 1));
        mx1 = fmaxf(mx1, __shfl_xor_sync(0xffffffffu, mx1, 2));

        float mnew0 = fmaxf(mrow0, mx0);
        float mnew1 = fmaxf(mrow1, mx1);
        float alpha0 = __expf(mrow0 - mnew0);
        float alpha1 = __expf(mrow1 - mnew1);
        mrow0 = mnew0; mrow1 = mnew1;

        float sum0 = 0.f, sum1 = 0.f;
#pragma unroll
        for (int nt = 0; nt < 8; nt++) {
            s[nt][0] = __expf(s[nt][0] - mnew0); sum0 += s[nt][0];
            s[nt][1] = __expf(s[nt][1] - mnew0); sum0 += s[nt][1];
            s[nt][2] = __expf(s[nt][2] - mnew1); sum1 += s[nt][2];
            s[nt][3] = __expf(s[nt][3] - mnew1); sum1 += s[nt][3];
        }
        sum0 += __shfl_xor_sync(0xffffffffu, sum0, 1);
        sum0 += __shfl_xor_sync(0xffffffffu, sum0, 2);
        sum1 += __shfl_xor_sync(0xffffffffu, sum1, 1);
        sum1 += __shfl_xor_sync(0xffffffffu, sum1, 2);

        lrow0 = lrow0 * alpha0 + sum0;
        lrow1 = lrow1 * alpha1 + sum1;

#pragma unroll
        for (int nt = 0; nt < 8; nt++) {
            o[nt][0] *= alpha0; o[nt][1] *= alpha0;
            o[nt][2] *= alpha1; o[nt][3] *= alpha1;
        }

        // C-frag -> A-frag: store P as fp16 pairs (one 32-bit STS per pair)
#pragma unroll
        for (int nt = 0; nt < 8; nt++) {
            int pc = nt * 8 + (la << 1);
            *(uint32_t*)(smc + AP_OFF + wg * 9216 + rloc * 144 + pc * 2) =
                pack_h2(s[nt][0], s[nt][1]);
            *(uint32_t*)(smc + AP_OFF + wg * 9216 + (rloc + 8) * 144 + pc * 2) =
                pack_h2(s[nt][2], s[nt][3]);
        }
        __syncwarp();

        // O += P * V (P via ldmatrix, V pairs via LDS.32)
#pragma unroll
        for (int ks = 0; ks < 4; ks++) {
            uint32_t a[4];
            LDSM4(a, psu + aoffQ + ks * 32);
#pragma unroll
            for (int nt = 0; nt < 8; nt++) {
                const int n = nt * 8 + nq;
                uint32_t bb[2];
                bb[0] = Vw[(ks * 8 + la) * 72 + n];
                bb[1] = Vw[(ks * 8 + la + 4) * 72 + n];
                mma_fp16(o[nt], a, bb);
            }
        }
        __syncthreads();   // all warps done with Ks/Vs before next fill
    }

    // Normalize and emit fp16 plane for the O-projection
    float inv0 = 1.f / lrow0;
    float inv1 = 1.f / lrow1;
    size_t r0 = (size_t)(b * kT + qb * 64 + rloc) * kE + hq * kHD;
    size_t r1 = (size_t)(b * kT + qb * 64 + rloc + 8) * kE + hq * kHD;
#pragma unroll
    for (int nt = 0; nt < 8; nt++) {
        int c = nt * 8 + (la << 1);
        *(uint32_t*)&aoh[r0 + c] = pack_h2(o[nt][0] * inv0, o[nt][1] * inv0);
        *(uint32_t*)&aoh[r1 + c] = pack_h2(o[nt][2] * inv1, o[nt][3] * inv1);
    }
}

// ---------------------------------------------------------------------------
// Launch
// ---------------------------------------------------------------------------
extern "C" void kernel_launch(void* const* d_in, const int* in_sizes, int n_in,
                              void* d_out, int out_size) {
    (void)in_sizes; (void)n_in; (void)out_size;
    const float* x   = (const float*)d_in[0];
    const float* Wq  = (const float*)d_in[1];
    const float* Wkv = (const float*)d_in[2];
    const float* Wo  = (const float*)d_in[3];
    float* out = (float*)d_out;

    float *q, *kvb;
    __half *xh, *wqh, *wkvh, *woh, *aoh;
    cudaGetSymbolAddress((void**)&q,    g_q);
    cudaGetSymbolAddress((void**)&kvb,  g_kv);
    cudaGetSymbolAddress((void**)&xh,   g_xh);
    cudaGetSymbolAddress((void**)&wqh,  g_wqh);
    cudaGetSymbolAddress((void**)&wkvh, g_wkvh);
    cudaGetSymbolAddress((void**)&woh,  g_woh);
    cudaGetSymbolAddress((void**)&aoh,  g_aoh);

    cudaFuncSetAttribute(gemm_f16,
                         cudaFuncAttributeMaxDynamicSharedMemorySize, GEMM_SMEM);
    cudaFuncSetAttribute(attn_kernel,
                         cudaFuncAttributeMaxDynamicSharedMemorySize, ATTN_SMEM);

    // fp16 casts of x and weights
    const int nx   = kM * kE / 4,   nwq = kE * kE / 4;
    const int nwkv = kKVN * kE / 4, nwo = kE * kE / 4;
    split1_kernel<<<(nx   + 255) / 256, 256>>>(x,   xh,   nx);
    split1_kernel<<<(nwq  + 255) / 256, 256>>>(Wq,  wqh,  nwq);
    split1_kernel<<<(nwkv + 255) / 256, 256>>>(Wkv, wkvh, nwkv);
    split1_kernel<<<(nwo  + 255) / 256, 256>>>(Wo,  woh,  nwo);

    // Projections: plain fp16 GEMMs (1 MMA per k16)
    gemm_f16<<<dim3(kE / 128,   kM / 128), 256, GEMM_SMEM>>>(xh, wqh,  q,   kE,   kE);
    gemm_f16<<<dim3(kKVN / 128, kM / 128), 256, GEMM_SMEM>>>(xh, wkvh, kvb, kKVN, kE);

    // Attention: fp16 m16n8k16, 2 query heads per CTA share one K/V stream
    attn_kernel<<<dim3(kT / 64, kB * kHQ / 2), 256, ATTN_SMEM>>>(q, kvb, aoh);

    // O-projection
    gemm_f16<<<dim3(kE / 128,   kM / 128), 256, GEMM_SMEM>>>(aoh, woh, out, kE, kE);
}

// round 12
// speedup vs baseline: 2.5227x; 1.0906x over previous
#include <cuda_runtime.h>
#include <cuda_fp16.h>
#include <math.h>
#include <stdint.h>

// Problem constants
#define kE   2048
#define kHQ  32
#define kHKV 8
#define kHD  64
#define kB   2
#define kT   2048
#define kM   (kB * kT)          // 4096 rows (B*T)
#define kKVN (2 * kHKV * kHD)   // 1024

#define QSCALE 0.1803368801111204f   // 0.125 * log2(e)

// ---------------------------------------------------------------------------
// Device-global scratch (allocation-free per harness rules)
// ---------------------------------------------------------------------------
__device__ __half g_qh[kM * kE];     // q projection, fp16, pre-scaled by QSCALE
__device__ __half g_kvh[kM * kKVN];  // kv projection fp16: k [0,512), v [512,1024)
__device__ __half g_xh[kM * kE];
__device__ __half g_wqh[kE * kE];
__device__ __half g_wkvh[kKVN * kE];
__device__ __half g_woh[kE * kE];
__device__ __half g_aoh[kM * kE];    // attention out, fp16

// ---------------------------------------------------------------------------
// Helpers
// ---------------------------------------------------------------------------
__device__ __forceinline__ uint32_t smem_u32(const void* p) {
    uint32_t a;
    asm("{ .reg .u64 t; cvta.to.shared.u64 t, %1; cvt.u32.u64 %0, t; }"
        : "=r"(a) : "l"(p));
    return a;
}

__device__ __forceinline__ void cp16(uint32_t saddr, const void* g) {
    asm volatile("cp.async.cg.shared.global [%0], [%1], 16;"
                 :: "r"(saddr), "l"(g) : "memory");
}
#define CP_COMMIT()  asm volatile("cp.async.commit_group;" ::: "memory")
#define CP_WAIT(n)   asm volatile("cp.async.wait_group %0;" :: "n"(n) : "memory")

#define LDSM4(r, addr)                                                        \
    asm volatile("ldmatrix.sync.aligned.m8n8.x4.shared.b16 {%0,%1,%2,%3}, [%4];" \
        : "=r"((r)[0]), "=r"((r)[1]), "=r"((r)[2]), "=r"((r)[3]) : "r"(addr))

// fp16 tensor op: D(16x8,f32) += A(16x16,f16) * B(16x8,f16)
__device__ __forceinline__ void mma_fp16(float* d, const uint32_t* a, const uint32_t* b) {
    asm volatile(
        "mma.sync.aligned.m16n8k16.row.col.f32.f16.f16.f32 "
        "{%0,%1,%2,%3},{%4,%5,%6,%7},{%8,%9},{%0,%1,%2,%3};\n"
        : "+f"(d[0]), "+f"(d[1]), "+f"(d[2]), "+f"(d[3])
        : "r"(a[0]), "r"(a[1]), "r"(a[2]), "r"(a[3]), "r"(b[0]), "r"(b[1]));
}

__device__ __forceinline__ uint32_t pack_h2(float a, float b) {
    __half2 h = __floats2half2_rn(a, b);
    return *reinterpret_cast<uint32_t*>(&h);
}

__device__ __forceinline__ float ex2(float x) {
    float r;
    asm("ex2.approx.ftz.f32 %0, %1;" : "=f"(r) : "f"(x));
    return r;
}

// ---------------------------------------------------------------------------
// Fused fp32 -> fp16 cast of x, Wq, Wkv, Wo (one launch)
// ---------------------------------------------------------------------------
#define C1 2097152              // x       float4 count
#define C2 (C1 + 1048576)       // + Wq
#define C3 (C2 + 524288)        // + Wkv
#define C4 (C3 + 1048576)       // + Wo

__global__ __launch_bounds__(256) void cast_all(
        const float* __restrict__ x,  const float* __restrict__ wq,
        const float* __restrict__ wkv, const float* __restrict__ wo,
        __half* __restrict__ xh, __half* __restrict__ wqh,
        __half* __restrict__ wkvh, __half* __restrict__ woh) {
    int i = blockIdx.x * 256 + threadIdx.x;
    if (i >= C4) return;
    const float* src; __half* dst; int off;
    if (i < C1)      { src = x;   dst = xh;   off = i; }
    else if (i < C2) { src = wq;  dst = wqh;  off = i - C1; }
    else if (i < C3) { src = wkv; dst = wkvh; off = i - C2; }
    else             { src = wo;  dst = woh;  off = i - C3; }
    float4 v = ((const float4*)src)[off];
    uint32_t* hp = (uint32_t*)dst;
    hp[2*off]   = pack_h2(v.x, v.y);
    hp[2*off+1] = pack_h2(v.z, v.w);
}

// ---------------------------------------------------------------------------
// GEMM: C[M,N] = scale * A[M,K] * W[N,K]^T, plain fp16 (1 MMA per k16).
// Output either fp32 (final) or fp16 (q / kv, with scale baked in).
// CTA 128x128, K-tile 32, 8 warps, 2-stage cp.async, ldmatrix fragments.
// ---------------------------------------------------------------------------
#define SPLANE_W 2560                       // 128 * 20 u32 words
#define SPLANE_B (SPLANE_W * 4)             // 10240 bytes
#define STAGE_B  (2 * SPLANE_B)             // A, W
#define GEMM_SMEM (2 * STAGE_B)             // 40960 bytes

__global__ __launch_bounds__(256) void gemm_f16(
        const __half* __restrict__ Ah, const __half* __restrict__ Whi,
        float* __restrict__ Cf, __half* __restrict__ Ch,
        float scale, int N, int K, int half_out) {
    extern __shared__ char smem[];
    const uint32_t sbase = smem_u32(smem);

    const int tid  = threadIdx.x;
    const int lane = tid & 31;
    const int wid  = tid >> 5;
    const int wm   = wid >> 1;        // 0..3
    const int wn   = wid & 1;         // 0..1
    const int m0   = blockIdx.y * 128;
    const int n0   = blockIdx.x * 128;

    float acc[2][8][4];
#pragma unroll
    for (int i = 0; i < 2; i++)
#pragma unroll
        for (int j = 0; j < 8; j++)
#pragma unroll
            for (int k = 0; k < 4; k++) acc[i][j][k] = 0.f;

    const size_t gs = (size_t)K * 2;  // bytes per global row
    const int crow  = tid >> 1;       // 0..127
    const int cbo   = (tid & 1) << 5; // 0 or 32 bytes

    const char* pA = (const char*)Ah;
    const char* pW = (const char*)Whi;

    const int NKT = K >> 5;

    auto copy_tile = [&](int s, int kt) {
        const uint32_t st = sbase + s * STAGE_B + crow * 80 + cbo;
        const size_t goA = (size_t)(m0 + crow) * gs + (size_t)kt * 64 + cbo;
        const size_t goW = (size_t)(n0 + crow) * gs + (size_t)kt * 64 + cbo;
        cp16(st,                 pA + goA);
        cp16(st + 16,            pA + goA + 16);
        cp16(st + SPLANE_B,      pW + goW);
        cp16(st + SPLANE_B + 16, pW + goW + 16);
    };

    copy_tile(0, 0);
    CP_COMMIT();

    // ldmatrix lane-address components
    const int lr8 = lane & 7;
    const int r8  = (lane >> 3) & 1;
    const int c4  = (lane >> 4) & 1;
    const uint32_t aoff0 = (uint32_t)((wm * 32 + lr8 + 8 * r8) * 80 + c4 * 16);
    const uint32_t aoff1 = aoff0 + 16 * 80;
    uint32_t boff[4];
#pragma unroll
    for (int np = 0; np < 4; np++)
        boff[np] = (uint32_t)((wn * 64 + np * 16 + lr8 + 8 * r8) * 80 + c4 * 16);

    const int rq = lane >> 2;
    const int wc = lane & 3;

    for (int kt = 0; kt < NKT; kt++) {
        if (kt + 1 < NKT) {
            copy_tile((kt + 1) & 1, kt + 1);
            CP_COMMIT();
            CP_WAIT(1);
        } else {
            CP_WAIT(0);
        }
        __syncthreads();

        const uint32_t stA = sbase + (kt & 1) * STAGE_B;
        const uint32_t stW = stA + SPLANE_B;

#pragma unroll
        for (int ks = 0; ks < 2; ks++) {
            const uint32_t ko = ks * 32;
            uint32_t ah[2][4];
            LDSM4(ah[0], stA + aoff0 + ko);
            LDSM4(ah[1], stA + aoff1 + ko);
            uint32_t bh[4][4];
#pragma unroll
            for (int np = 0; np < 4; np++)
                LDSM4(bh[np], stW + boff[np] + ko);
#pragma unroll
            for (int nt = 0; nt < 8; nt++) {
                const int np = nt >> 1, g = nt & 1;
                uint32_t bhf[2] = {bh[np][g], bh[np][2 + g]};
                mma_fp16(acc[0][nt], ah[0], bhf);
                mma_fp16(acc[1][nt], ah[1], bhf);
            }
        }
        __syncthreads();
    }

    if (half_out) {
#pragma unroll
        for (int mt = 0; mt < 2; mt++) {
            const int r = m0 + wm * 32 + mt * 16 + rq;
#pragma unroll
            for (int nt = 0; nt < 8; nt++) {
                const int c = n0 + wn * 64 + nt * 8 + (wc << 1);
                *(uint32_t*)&Ch[(size_t)r * N + c] =
                    pack_h2(acc[mt][nt][0] * scale, acc[mt][nt][1] * scale);
                *(uint32_t*)&Ch[(size_t)(r + 8) * N + c] =
                    pack_h2(acc[mt][nt][2] * scale, acc[mt][nt][3] * scale);
            }
        }
    } else {
#pragma unroll
        for (int mt = 0; mt < 2; mt++) {
            const int r = m0 + wm * 32 + mt * 16 + rq;
#pragma unroll
            for (int nt = 0; nt < 8; nt++) {
                const int c = n0 + wn * 64 + nt * 8 + (wc << 1);
                *(float2*)&Cf[(size_t)r * N + c]       = make_float2(acc[mt][nt][0], acc[mt][nt][1]);
                *(float2*)&Cf[(size_t)(r + 8) * N + c] = make_float2(acc[mt][nt][2], acc[mt][nt][3]);
            }
        }
    }
}

// ---------------------------------------------------------------------------
// Flash attention (causal, GQA), fp16 m16n8k16.
// - Inputs pre-converted fp16 (Q pre-scaled by 0.125*log2e -> exp2 softmax)
// - P stays in registers (C-frag == A-frag layout identity)
// - 2 query heads per CTA share the K/V stream
// - LPT: heaviest query blocks launch first
// ---------------------------------------------------------------------------
#define AQ_OFF 0          // Qs: 2 heads * 64 rows * 144B = 18432
#define AK_OFF 18432      // Ks: 64 * 144                 = 9216
#define AV_OFF 27648      // Vp: 32 * 288                 = 9216
#define ATTN_SMEM 36864

__global__ __launch_bounds__(256) void attn_kernel(
        const __half* __restrict__ qh, const __half* __restrict__ kvh,
        __half* __restrict__ aoh) {
    extern __shared__ char smc[];
    const uint32_t sb = smem_u32(smc);

    const int tid  = threadIdx.x;
    const int lane = tid & 31;
    const int w    = tid >> 5;          // 0..7
    const int wg   = w >> 2;            // head sub-index 0/1
    const int wl   = w & 3;             // warp within head
    const int qb   = gridDim.x - 1 - blockIdx.x;   // LPT: heavy blocks first
    const int pidx = blockIdx.y;        // (b, head-pair)
    const int b    = pidx >> 4;
    const int hp   = pidx & 15;
    const int hq   = hp * 2 + wg;
    const int hkv  = hp >> 1;

    const uint32_t qsu = sb + AQ_OFF + wg * 9216;
    const uint32_t ksu = sb + AK_OFF;
    uint32_t* Vw = (uint32_t*)(smc + AV_OFF);

    // ---- Load both heads' Q tiles: pure 16B copies (fp16, pre-scaled)
    {
        const int half  = tid >> 7;               // 0/1 -> head
        const int hrow  = (tid & 127) >> 3;       // 0..15
        const int hcol  = (tid & 7) * 8;          // halves, 0..56
        const int hqh   = hp * 2 + half;
        char* Qdst = smc + AQ_OFF + half * 9216;
#pragma unroll
        for (int p = 0; p < 4; p++) {
            int row = p * 16 + hrow;
            const uint4 v = *(const uint4*)
                &qh[((size_t)(b * kT + qb * 64 + row)) * kE + hqh * kHD + hcol];
            *(uint4*)(Qdst + row * 144 + hcol * 2) = v;
        }
    }

    float mrow0 = -INFINITY, mrow1 = -INFINITY;
    float lrow0 = 0.f, lrow1 = 0.f;
    float o[8][4];
#pragma unroll
    for (int nt = 0; nt < 8; nt++)
#pragma unroll
        for (int i = 0; i < 4; i++) o[nt][i] = 0.f;

    const int rloc = wl * 16 + (lane >> 2);   // warp's rows rloc, rloc+8 (0..63)

    // ldmatrix lane addresses (byte offsets; +32 per k16 step)
    const int lr8 = lane & 7;
    const int r8  = (lane >> 3) & 1;
    const int c4  = (lane >> 4) & 1;
    const uint32_t aoffQ = (uint32_t)((wl * 16 + lr8 + 8 * r8) * 144 + c4 * 16);
    uint32_t boffK[4];
#pragma unroll
    for (int np = 0; np < 4; np++)
        boffK[np] = (uint32_t)((np * 16 + lr8 + 8 * r8) * 144 + c4 * 16);

    const int la = lane & 3;
    const int nq = lane >> 2;

    // K fill mapping: 2 passes x 32 rows; V fill: one pass, k-pair interleave
    const int krow = tid >> 3;          // 0..31
    const int kcol = (tid & 7) * 8;     // halves

    for (int j = 0; j <= qb; j++) {
        // K tile: straight fp16 copy, 64 rows x 64 halves
#pragma unroll
        for (int p = 0; p < 2; p++) {
            int row = p * 32 + krow;
            const uint4 v = *(const uint4*)
                &kvh[((size_t)(b * kT + j * 64 + row)) * kKVN + hkv * kHD + kcol];
            *(uint4*)(smc + AK_OFF + row * 144 + kcol * 2) = v;
        }
        // V tile: interleave rows (2k, 2k+1) into half2 words
        {
            const int k2 = krow;              // 0..31
            size_t ba = ((size_t)(b * kT + j * 64 + 2 * k2)) * kKVN + hkv * kHD + 512 + kcol;
            uint4 va = *(const uint4*)&kvh[ba];
            uint4 vb = *(const uint4*)&kvh[ba + kKVN];
            uint4 o0, o1;
            o0.x = __byte_perm(va.x, vb.x, 0x5410);
            o0.y = __byte_perm(va.x, vb.x, 0x7632);
            o0.z = __byte_perm(va.y, vb.y, 0x5410);
            o0.w = __byte_perm(va.y, vb.y, 0x7632);
            o1.x = __byte_perm(va.z, vb.z, 0x5410);
            o1.y = __byte_perm(va.z, vb.z, 0x7632);
            o1.z = __byte_perm(va.w, vb.w, 0x5410);
            o1.w = __byte_perm(va.w, vb.w, 0x7632);
            *(uint4*)(smc + AV_OFF + k2 * 288 + kcol * 4)      = o0;
            *(uint4*)(smc + AV_OFF + k2 * 288 + kcol * 4 + 16) = o1;
        }
        __syncthreads();

        // S = Q * K^T  (fp16 m16n8k16, 4 k-steps); logits already in log2 domain
        float s[8][4];
#pragma unroll
        for (int nt = 0; nt < 8; nt++) { s[nt][0] = s[nt][1] = s[nt][2] = s[nt][3] = 0.f; }

#pragma unroll
        for (int ks = 0; ks < 4; ks++) {
            const uint32_t ko = ks * 32;
            uint32_t a[4];
            LDSM4(a, qsu + aoffQ + ko);
#pragma unroll
            for (int np = 0; np < 4; np++) {
                uint32_t kb[4];
                LDSM4(kb, ksu + boffK[np] + ko);
#pragma unroll
                for (int g = 0; g < 2; g++) {
                    uint32_t bb[2] = {kb[g], kb[2 + g]};
                    mma_fp16(s[2 * np + g], a, bb);
                }
            }
        }

        // Causal mask on the diagonal block
        if (j == qb) {
#pragma unroll
            for (int nt = 0; nt < 8; nt++) {
                int c0 = nt * 8 + (la << 1);
                if (c0     > rloc)     s[nt][0] = -INFINITY;
                if (c0 + 1 > rloc)     s[nt][1] = -INFINITY;
                if (c0     > rloc + 8) s[nt][2] = -INFINITY;
                if (c0 + 1 > rloc + 8) s[nt][3] = -INFINITY;
            }
        }

        // Online softmax (exp2 domain)
        float mx0 = -INFINITY, mx1 = -INFINITY;
#pragma unroll
        for (int nt = 0; nt < 8; nt++) {
            mx0 = fmaxf(mx0, fmaxf(s[nt][0], s[nt][1]));
            mx1 = fmaxf(mx1, fmaxf(s[nt][2], s[nt][3]));
        }
        mx0 = fmaxf(mx0, __shfl_xor_sync(0xffffffffu, mx0, 1));
        mx0 = fmaxf(mx0, __shfl_xor_sync(0xffffffffu, mx0, 2));
        mx1 = fmaxf(mx1, __shfl_xor_sync(0xffffffffu, mx1, 1));
        mx1 = fmaxf(mx1, __shfl_xor_sync(0xffffffffu, mx1, 2));

        float mnew0 = fmaxf(mrow0, mx0);
        float mnew1 = fmaxf(mrow1, mx1);
        float alpha0 = ex2(mrow0 - mnew0);
        float alpha1 = ex2(mrow1 - mnew1);
        mrow0 = mnew0; mrow1 = mnew1;

        float sum0 = 0.f, sum1 = 0.f;
#pragma unroll
        for (int nt = 0; nt < 8; nt++) {
            s[nt][0] = ex2(s[nt][0] - mnew0); sum0 += s[nt][0];
            s[nt][1] = ex2(s[nt][1] - mnew0); sum0 += s[nt][1];
            s[nt][2] = ex2(s[nt][2] - mnew1); sum1 += s[nt][2];
            s[nt][3] = ex2(s[nt][3] - mnew1); sum1 += s[nt][3];
        }
        sum0 += __shfl_xor_sync(0xffffffffu, sum0, 1);
        sum0 += __shfl_xor_sync(0xffffffffu, sum0, 2);
        sum1 += __shfl_xor_sync(0xffffffffu, sum1, 1);
        sum1 += __shfl_xor_sync(0xffffffffu, sum1, 2);

        lrow0 = lrow0 * alpha0 + sum0;
        lrow1 = lrow1 * alpha1 + sum1;

#pragma unroll
        for (int nt = 0; nt < 8; nt++) {
            o[nt][0] *= alpha0; o[nt][1] *= alpha0;
            o[nt][2] *= alpha1; o[nt][3] *= alpha1;
        }

        // O += P * V — P packed directly from S registers (C-frag == A-frag)
#pragma unroll
        for (int ks = 0; ks < 4; ks++) {
            uint32_t a[4];
            a[0] = pack_h2(s[2*ks][0],     s[2*ks][1]);
            a[1] = pack_h2(s[2*ks][2],     s[2*ks][3]);
            a[2] = pack_h2(s[2*ks+1][0],   s[2*ks+1][1]);
            a[3] = pack_h2(s[2*ks+1][2],   s[2*ks+1][3]);
#pragma unroll
            for (int nt = 0; nt < 8; nt++) {
                const int n = nt * 8 + nq;
                uint32_t bb[2];
                bb[0] = Vw[(ks * 8 + la) * 72 + n];
                bb[1] = Vw[(ks * 8 + la + 4) * 72 + n];
                mma_fp16(o[nt], a, bb);
            }
        }
        __syncthreads();   // all warps done with Ks/Vs before next fill
    }

    // Normalize and emit fp16 plane for the O-projection
    float inv0 = 1.f / lrow0;
    float inv1 = 1.f / lrow1;
    size_t r0 = (size_t)(b * kT + qb * 64 + rloc) * kE + hq * kHD;
    size_t r1 = (size_t)(b * kT + qb * 64 + rloc + 8) * kE + hq * kHD;
#pragma unroll
    for (int nt = 0; nt < 8; nt++) {
        int c = nt * 8 + (la << 1);
        *(uint32_t*)&aoh[r0 + c] = pack_h2(o[nt][0] * inv0, o[nt][1] * inv0);
        *(uint32_t*)&aoh[r1 + c] = pack_h2(o[nt][2] * inv1, o[nt][3] * inv1);
    }
}

// ---------------------------------------------------------------------------
// Launch
// ---------------------------------------------------------------------------
extern "C" void kernel_launch(void* const* d_in, const int* in_sizes, int n_in,
                              void* d_out, int out_size) {
    (void)in_sizes; (void)n_in; (void)out_size;
    const float* x   = (const float*)d_in[0];
    const float* Wq  = (const float*)d_in[1];
    const float* Wkv = (const float*)d_in[2];
    const float* Wo  = (const float*)d_in[3];
    float* out = (float*)d_out;

    __half *qh, *kvh, *xh, *wqh, *wkvh, *woh, *aoh;
    cudaGetSymbolAddress((void**)&qh,   g_qh);
    cudaGetSymbolAddress((void**)&kvh,  g_kvh);
    cudaGetSymbolAddress((void**)&xh,   g_xh);
    cudaGetSymbolAddress((void**)&wqh,  g_wqh);
    cudaGetSymbolAddress((void**)&wkvh, g_wkvh);
    cudaGetSymbolAddress((void**)&woh,  g_woh);
    cudaGetSymbolAddress((void**)&aoh,  g_aoh);

    cudaFuncSetAttribute(gemm_f16,
                         cudaFuncAttributeMaxDynamicSharedMemorySize, GEMM_SMEM);
    cudaFuncSetAttribute(attn_kernel,
                         cudaFuncAttributeMaxDynamicSharedMemorySize, ATTN_SMEM);

    // One fused cast launch (x, Wq, Wkv, Wo -> fp16)
    cast_all<<<(C4 + 255) / 256, 256>>>(x, Wq, Wkv, Wo, xh, wqh, wkvh, woh);

    // Projections: plain fp16 GEMMs; q/kv emit fp16 (q pre-scaled for exp2)
    gemm_f16<<<dim3(kE / 128,   kM / 128), 256, GEMM_SMEM>>>(
        xh, wqh,  nullptr, qh,  QSCALE, kE,   kE, 1);
    gemm_f16<<<dim3(kKVN / 128, kM / 128), 256, GEMM_SMEM>>>(
        xh, wkvh, nullptr, kvh, 1.0f,   kKVN, kE, 1);

    // Attention (LPT order, P-in-registers, exp2 softmax)
    attn_kernel<<<dim3(kT / 64, kB * kHQ / 2), 256, ATTN_SMEM>>>(qh, kvh, aoh);

    // O-projection (fp32 out)
    gemm_f16<<<dim3(kE / 128,   kM / 128), 256, GEMM_SMEM>>>(
        aoh, woh, out, nullptr, 1.0f, kE, kE, 0);
}